// round 1
// baseline (speedup 1.0000x reference)
#include <cuda_runtime.h>
#include <math.h>

// Problem constants
#define BB 4
#define NT 96
#define CC 256
#define HH 8
#define DD 32
#define NN (NT*NT)          // 9216
#define MM (BB*NN)          // 36864
#define FIVEC (5*CC)        // 1280
#define DEPTH 4
#define SCALE_F 8.83883476483184405556f  // 50/sqrt(32)

// ---------------- device global scratch (no allocations allowed) ----------------
__device__ float g_bufA[MM*CC];                 // 37.75 MB
__device__ float g_bufB[MM*CC];                 // 37.75 MB
__device__ float g_qkv[MM*FIVEC];               // 188.7 MB
__device__ float g_S[BB*HH*NT*NN];              // 113.2 MB  [b,h,i,j,p]
__device__ float g_part[2*1024];
__device__ float g_ms[2];                       // mean, inv_std
__device__ float g_pool[BB*NT*CC];              // per-(b,i) partial pools
__device__ int   g_isI64;

// ---------------- adj dtype detection ----------------
// adj values are 0/1. If the buffer is int64, every odd 32-bit word (high half)
// is zero. If int32, odd words are real values (~half nonzero, P(all zero)~2^-18000).
__global__ void detect_adj_kern(const unsigned int* __restrict__ a, int n) {
    __shared__ int any;
    if (threadIdx.x == 0) any = 0;
    __syncthreads();
    int nz = 0;
    for (int i = 1 + 2*threadIdx.x; i < n; i += 2*blockDim.x)
        nz |= (a[i] != 0u);
    if (nz) any = 1;
    __syncthreads();
    if (threadIdx.x == 0) g_isI64 = any ? 0 : 1;
}

// ---------------- embedding gather ----------------
__global__ void embed_kern(const int* __restrict__ adj,
                           const float* __restrict__ emb,
                           float* __restrict__ X) {
    int i64 = g_isI64;
    int total = MM * (CC/4);
    for (int t = blockIdx.x*blockDim.x + threadIdx.x; t < total;
         t += gridDim.x*blockDim.x) {
        int m = t >> 6;
        int c4 = t & 63;
        int a = i64 ? adj[2*m] : adj[m];
        float4 v = ((const float4*)emb)[a*(CC/4) + c4];
        ((float4*)X)[m*(CC/4) + c4] = v;
    }
}

// ---------------- global mean/std reduction ----------------
__global__ void red1_kern(const float* __restrict__ X) {
    float s = 0.f, s2 = 0.f;
    for (int i = blockIdx.x*blockDim.x + threadIdx.x; i < MM*CC;
         i += gridDim.x*blockDim.x) {
        float v = X[i];
        s += v; s2 += v*v;
    }
    __shared__ float sh1[256], sh2[256];
    int t = threadIdx.x;
    sh1[t] = s; sh2[t] = s2;
    __syncthreads();
    for (int o = 128; o; o >>= 1) {
        if (t < o) { sh1[t] += sh1[t+o]; sh2[t] += sh2[t+o]; }
        __syncthreads();
    }
    if (t == 0) { g_part[blockIdx.x] = sh1[0]; g_part[1024 + blockIdx.x] = sh2[0]; }
}

__global__ void red2_kern() {
    __shared__ double sh1[256], sh2[256];
    int t = threadIdx.x;
    double s = 0.0, s2 = 0.0;
    for (int i = t; i < 1024; i += 256) { s += (double)g_part[i]; s2 += (double)g_part[1024+i]; }
    sh1[t] = s; sh2[t] = s2;
    __syncthreads();
    for (int o = 128; o; o >>= 1) {
        if (t < o) { sh1[t] += sh1[t+o]; sh2[t] += sh2[t+o]; }
        __syncthreads();
    }
    if (t == 0) {
        double n = (double)MM * (double)CC;
        double mean = sh1[0] / n;
        double var  = (sh2[0] - sh1[0]*sh1[0]/n) / (n - 1.0);
        g_ms[0] = (float)mean;
        g_ms[1] = (float)(1.0 / sqrt(var));
    }
}

// ---------------- QKV GEMM: [36864 x 256] @ W^T -> [36864 x 1280], fused norm ----------------
__global__ void __launch_bounds__(256)
qkv_gemm_kern(const float* __restrict__ X, const float* __restrict__ W) {
    __shared__ float As[32][65];
    __shared__ float Bs[32][65];
    float mean = g_ms[0], istd = g_ms[1];
    int mb = blockIdx.x;      // 0..575
    int nb = blockIdx.y;      // 0..19
    int t = threadIdx.x;
    int ty = t >> 4, tx = t & 15;
    int lr = t >> 5;          // 0..7
    int lk = t & 31;
    float acc[4][4] = {};
    for (int k0 = 0; k0 < CC; k0 += 32) {
        #pragma unroll
        for (int r = 0; r < 8; r++) {
            int m = mb*64 + lr + r*8;
            float v = X[m*CC + k0 + lk];
            As[lk][lr + r*8] = (v - mean) * istd;
        }
        #pragma unroll
        for (int r = 0; r < 8; r++) {
            int nn = nb*64 + lr + r*8;
            Bs[lk][lr + r*8] = W[nn*CC + k0 + lk];
        }
        __syncthreads();
        #pragma unroll 8
        for (int k = 0; k < 32; k++) {
            float a[4], b[4];
            #pragma unroll
            for (int i = 0; i < 4; i++) a[i] = As[k][ty + 16*i];
            #pragma unroll
            for (int i = 0; i < 4; i++) b[i] = Bs[k][tx + 16*i];
            #pragma unroll
            for (int i = 0; i < 4; i++)
                #pragma unroll
                for (int j = 0; j < 4; j++)
                    acc[i][j] += a[i]*b[j];
        }
        __syncthreads();
    }
    #pragma unroll
    for (int i = 0; i < 4; i++) {
        int m = mb*64 + ty + 16*i;
        #pragma unroll
        for (int j = 0; j < 4; j++) {
            int nn = nb*64 + tx + 16*j;
            g_qkv[(size_t)m*FIVEC + nn] = acc[i][j];
        }
    }
}

// ---------------- S1: per (b,h,i) CTA, S1[j,p] = Q_i[j,:]·K1_i[p,:] ----------------
__global__ void __launch_bounds__(256)
s1_kern() {
    __shared__ float Qs[96*33];
    __shared__ float Ks[96*33];
    int bhi = blockIdx.x;
    int i = bhi % NT;
    int bh = bhi / NT;
    int h = bh % HH, b = bh / HH;
    int baseQ = (b*NN + i*NT)*FIVEC + h*DD;       // + j*1280 + d
    int baseK = baseQ + CC;                       // k1 chunk
    int t = threadIdx.x;
    for (int idx = t; idx < 96*32; idx += 256) {
        int r = idx >> 5, d = idx & 31;
        Qs[r*33 + d] = g_qkv[baseQ + r*FIVEC + d];
        Ks[r*33 + d] = g_qkv[baseK + r*FIVEC + d];
    }
    __syncthreads();
    int ty = t >> 4, tx = t & 15;
    float acc[6][6] = {};
    #pragma unroll 4
    for (int d = 0; d < 32; d++) {
        float a[6], bb[6];
        #pragma unroll
        for (int r = 0; r < 6; r++) a[r] = Qs[(ty + 16*r)*33 + d];
        #pragma unroll
        for (int c = 0; c < 6; c++) bb[c] = Ks[(tx + 16*c)*33 + d];
        #pragma unroll
        for (int r = 0; r < 6; r++)
            #pragma unroll
            for (int c = 0; c < 6; c++)
                acc[r][c] += a[r]*bb[c];
    }
    size_t base = (size_t)(bh*NT + i) * NN;       // + j*96 + p
    #pragma unroll
    for (int r = 0; r < 6; r++) {
        int j = ty + 16*r;
        #pragma unroll
        for (int c = 0; c < 6; c++) {
            int p = tx + 16*c;
            g_S[base + j*NT + p] = acc[r][c];
        }
    }
}

// ---------------- S2 + softmax + O2: per (b,h,j) CTA ----------------
// smem: Qs[96*33] + Ks[96*33] + Ss[96*97]  = 62592 bytes (dynamic)
__global__ void __launch_bounds__(256)
s2_soft_o2_kern(float* __restrict__ Xout) {
    extern __shared__ float sm[];
    float* Qs = sm;
    float* Ks = sm + 96*33;
    float* Ss = Ks + 96*33;
    int bhj = blockIdx.x;
    int j = bhj % NT;
    int bh = bhj / NT;
    int h = bh % HH, b = bh / HH;
    int t = threadIdx.x;
    int baseQ = (b*NN + j)*FIVEC + h*DD;          // + i*(96*1280) + d
    int baseK2 = baseQ + 2*CC;
    for (int idx = t; idx < 96*32; idx += 256) {
        int r = idx >> 5, d = idx & 31;
        Qs[r*33 + d] = g_qkv[baseQ  + r*NT*FIVEC + d];
        Ks[r*33 + d] = g_qkv[baseK2 + r*NT*FIVEC + d];
    }
    __syncthreads();
    int ty = t >> 4, tx = t & 15;
    size_t sBase = (size_t)bh * NT * NN + (size_t)j * NT;   // + i*NN + p
    {
        float acc[6][6] = {};
        #pragma unroll 4
        for (int d = 0; d < 32; d++) {
            float a[6], bb[6];
            #pragma unroll
            for (int r = 0; r < 6; r++) a[r] = Qs[(ty + 16*r)*33 + d];
            #pragma unroll
            for (int c = 0; c < 6; c++) bb[c] = Ks[(tx + 16*c)*33 + d];
            #pragma unroll
            for (int r = 0; r < 6; r++)
                #pragma unroll
                for (int c = 0; c < 6; c++)
                    acc[r][c] += a[r]*bb[c];
        }
        #pragma unroll
        for (int r = 0; r < 6; r++) {
            int i = ty + 16*r;
            #pragma unroll
            for (int c = 0; c < 6; c++) {
                int p = tx + 16*c;
                Ss[i*97 + p] = (g_S[sBase + (size_t)i*NN + p] + acc[r][c]) * SCALE_F;
            }
        }
    }
    __syncthreads();
    // softmax per row i over p (96), also write A back to g_S for the O1 pass
    int warp = t >> 5, lane = t & 31;
    for (int i = warp; i < 96; i += 8) {
        float v0 = Ss[i*97 + lane];
        float v1 = Ss[i*97 + 32 + lane];
        float v2 = Ss[i*97 + 64 + lane];
        float mx = fmaxf(v0, fmaxf(v1, v2));
        #pragma unroll
        for (int o = 16; o; o >>= 1) mx = fmaxf(mx, __shfl_xor_sync(0xffffffffu, mx, o));
        v0 = __expf(v0 - mx); v1 = __expf(v1 - mx); v2 = __expf(v2 - mx);
        float s = v0 + v1 + v2;
        #pragma unroll
        for (int o = 16; o; o >>= 1) s += __shfl_xor_sync(0xffffffffu, s, o);
        float inv = 1.f / s;
        v0 *= inv; v1 *= inv; v2 *= inv;
        Ss[i*97 + lane] = v0;
        Ss[i*97 + 32 + lane] = v1;
        Ss[i*97 + 64 + lane] = v2;
        g_S[sBase + (size_t)i*NN + lane]      = v0;
        g_S[sBase + (size_t)i*NN + 32 + lane] = v1;
        g_S[sBase + (size_t)i*NN + 64 + lane] = v2;
    }
    __syncthreads();
    // reload Ks with V2_j[p][d]
    for (int idx = t; idx < 96*32; idx += 256) {
        int r = idx >> 5, d = idx & 31;
        Ks[r*33 + d] = g_qkv[baseQ + 4*CC + r*NT*FIVEC + d];
    }
    __syncthreads();
    // O2[i][d] = sum_p A[i][p] * V2[p][d]
    int d = t & 31, i0 = t >> 5;
    for (int i = i0; i < 96; i += 16) {
        float a0 = 0.f, a1 = 0.f;
        #pragma unroll 8
        for (int p = 0; p < 96; p++) {
            float vv = Ks[p*33 + d];
            a0 += Ss[i*97 + p] * vv;
            a1 += Ss[(i+8)*97 + p] * vv;
        }
        int o0 = (b*NN + i*NT + j)*CC + h*DD + d;
        Xout[o0] = a0;
        Xout[o0 + 8*NT*CC] = a1;
    }
}

// ---------------- O1 accumulate: per (b,h,i) CTA ----------------
// smem: As[96*97] + Vs[96*33] = 49920 bytes (dynamic)
__global__ void __launch_bounds__(256)
o1_kern(float* __restrict__ Xout) {
    extern __shared__ float sm[];
    float* As = sm;
    float* Vs = sm + 96*97;
    int bhi = blockIdx.x;
    int i = bhi % NT;
    int bh = bhi / NT;
    int h = bh % HH, b = bh / HH;
    int t = threadIdx.x;
    size_t aBase = (size_t)(bh*NT + i) * NN;
    for (int idx = t; idx < 96*96; idx += 256) {
        int r = idx / 96, p = idx % 96;
        As[r*97 + p] = g_S[aBase + idx];
    }
    int baseV = (b*NN + i*NT)*FIVEC + 3*CC + h*DD;
    for (int idx = t; idx < 96*32; idx += 256) {
        int r = idx >> 5, d = idx & 31;
        Vs[r*33 + d] = g_qkv[baseV + r*FIVEC + d];
    }
    __syncthreads();
    int d = t & 31, j0 = t >> 5;
    for (int j = j0; j < 96; j += 16) {
        float a0 = 0.f, a1 = 0.f;
        #pragma unroll 8
        for (int p = 0; p < 96; p++) {
            float vv = Vs[p*33 + d];
            a0 += As[j*97 + p] * vv;
            a1 += As[(j+8)*97 + p] * vv;
        }
        int o0 = (b*NN + i*NT + j)*CC + h*DD + d;
        Xout[o0] += a0;
        Xout[o0 + 8*CC] += a1;
    }
}

// ---------------- pooling + head ----------------
__global__ void pool1_kern(const float* __restrict__ X) {
    int bi = blockIdx.x;                // b*96 + i
    int b = bi / NT, i = bi % NT;
    int c = threadIdx.x;
    float s = 0.f;
    for (int j = 0; j < NT; j++)
        s += X[(b*NN + i*NT + j)*CC + c];
    g_pool[bi*CC + c] = s;
}

__global__ void pool2_head_kern(const float* __restrict__ W,
                                const float* __restrict__ bias,
                                float* __restrict__ out) {
    int b = blockIdx.x;
    __shared__ float xb[CC];
    int c = threadIdx.x;
    float s = 0.f;
    for (int i = 0; i < NT; i++)
        s += g_pool[(b*NT + i)*CC + c];
    xb[c] = s * (1.f / (float)NN);
    __syncthreads();
    float acc = bias[c];
    #pragma unroll 8
    for (int ci = 0; ci < CC; ci++)
        acc += xb[ci] * W[c*CC + ci];
    out[b*CC + c] = acc;
}

// ---------------- launch ----------------
extern "C" void kernel_launch(void* const* d_in, const int* in_sizes, int n_in,
                              void* d_out, int out_size) {
    const int*   adj   = (const int*)d_in[0];
    const float* emb   = (const float*)d_in[1];
    const float* qkvw  = (const float*)d_in[2];
    const float* headw = (const float*)d_in[3];
    const float* headb = (const float*)d_in[4];
    float* out = (float*)d_out;

    float *bufA, *bufB;
    cudaGetSymbolAddress((void**)&bufA, g_bufA);
    cudaGetSymbolAddress((void**)&bufB, g_bufB);

    cudaFuncSetAttribute(s2_soft_o2_kern, cudaFuncAttributeMaxDynamicSharedMemorySize, 96*33*4*2 + 96*97*4);
    cudaFuncSetAttribute(o1_kern,         cudaFuncAttributeMaxDynamicSharedMemorySize, 96*97*4 + 96*33*4);

    detect_adj_kern<<<1, 256>>>((const unsigned int*)adj, MM/CC * 0 + BB*NN); // n = 36864
    embed_kern<<<1024, 256>>>(adj, emb, bufA);

    for (int l = 0; l < DEPTH; l++) {
        float* cur = (l & 1) ? bufB : bufA;
        float* nxt = (l & 1) ? bufA : bufB;
        red1_kern<<<1024, 256>>>(cur);
        red2_kern<<<1, 256>>>();
        qkv_gemm_kern<<<dim3(MM/64, FIVEC/64), 256>>>(cur, qkvw + (size_t)l*FIVEC*CC);
        s1_kern<<<BB*HH*NT, 256>>>();
        s2_soft_o2_kern<<<BB*HH*NT, 256, 96*33*4*2 + 96*97*4>>>(nxt);
        o1_kern<<<BB*HH*NT, 256, 96*97*4 + 96*33*4>>>(nxt);
    }
    // depth=4 even -> final activations are in bufA
    pool1_kern<<<BB*NT, 256>>>(bufA);
    pool2_head_kern<<<BB, 256>>>(headw, headb, out);
}

// round 2
// speedup vs baseline: 1.3599x; 1.3599x over previous
#include <cuda_runtime.h>
#include <math.h>

// Problem constants
#define BB 4
#define NT 96
#define CC 256
#define HH 8
#define DD 32
#define NN (NT*NT)          // 9216
#define MM (BB*NN)          // 36864
#define FIVEC (5*CC)        // 1280
#define DEPTH 4
// scale * log2(e): softmax computed in base-2 domain (exact same probabilities)
#define SCALE_L2E (8.83883476483184405556f * 1.44269504088896340736f)

typedef unsigned long long u64;

// ---------------- f32x2 helpers (FFMA2 path, sm_103a) ----------------
__device__ __forceinline__ u64 dup2(float x) {
    u64 r; asm("mov.b64 %0, {%1, %1};" : "=l"(r) : "f"(x)); return r;
}
__device__ __forceinline__ void unpack2(u64 v, float& lo, float& hi) {
    asm("mov.b64 {%0, %1}, %2;" : "=f"(lo), "=f"(hi) : "l"(v));
}
__device__ __forceinline__ void fma2(u64& d, u64 a, u64 b) {
    asm("fma.rn.f32x2 %0, %1, %2, %0;" : "+l"(d) : "l"(a), "l"(b));
}
__device__ __forceinline__ u64 add2(u64 a, u64 b) {
    u64 r; asm("add.rn.f32x2 %0, %1, %2;" : "=l"(r) : "l"(a), "l"(b)); return r;
}
__device__ __forceinline__ u64 mul2(u64 a, u64 b) {
    u64 r; asm("mul.rn.f32x2 %0, %1, %2;" : "=l"(r) : "l"(a), "l"(b)); return r;
}
__device__ __forceinline__ float ex2f(float x) {
    float r; asm("ex2.approx.ftz.f32 %0, %1;" : "=f"(r) : "f"(x)); return r;
}

// ---------------- device global scratch ----------------
__device__ float g_bufA[MM*CC];
__device__ float g_bufB[MM*CC];
__device__ float g_qkv[MM*FIVEC];
__device__ float g_S[BB*HH*NT*NN];              // [b,h,i,j,p]
__device__ float g_part[2*1024];
__device__ float g_ms[2];
__device__ float g_pool[BB*NT*CC];
__device__ int   g_isI64;

// ---------------- adj dtype detection ----------------
__global__ void detect_adj_kern(const unsigned int* __restrict__ a, int n) {
    __shared__ int any;
    if (threadIdx.x == 0) any = 0;
    __syncthreads();
    int nz = 0;
    for (int i = 1 + 2*threadIdx.x; i < n; i += 2*blockDim.x)
        nz |= (a[i] != 0u);
    if (nz) any = 1;
    __syncthreads();
    if (threadIdx.x == 0) g_isI64 = any ? 0 : 1;
}

// ---------------- embedding gather ----------------
__global__ void embed_kern(const int* __restrict__ adj,
                           const float* __restrict__ emb,
                           float* __restrict__ X) {
    int i64 = g_isI64;
    int total = MM * (CC/4);
    for (int t = blockIdx.x*blockDim.x + threadIdx.x; t < total;
         t += gridDim.x*blockDim.x) {
        int m = t >> 6;
        int c4 = t & 63;
        int a = i64 ? adj[2*m] : adj[m];
        float4 v = ((const float4*)emb)[a*(CC/4) + c4];
        ((float4*)X)[m*(CC/4) + c4] = v;
    }
}

// ---------------- global mean/std reduction ----------------
__global__ void red1_kern(const float* __restrict__ X) {
    float s = 0.f, s2 = 0.f;
    for (int i = blockIdx.x*blockDim.x + threadIdx.x; i < MM*CC;
         i += gridDim.x*blockDim.x) {
        float v = X[i];
        s += v; s2 += v*v;
    }
    __shared__ float sh1[256], sh2[256];
    int t = threadIdx.x;
    sh1[t] = s; sh2[t] = s2;
    __syncthreads();
    for (int o = 128; o; o >>= 1) {
        if (t < o) { sh1[t] += sh1[t+o]; sh2[t] += sh2[t+o]; }
        __syncthreads();
    }
    if (t == 0) { g_part[blockIdx.x] = sh1[0]; g_part[1024 + blockIdx.x] = sh2[0]; }
}

__global__ void red2_kern() {
    __shared__ double sh1[256], sh2[256];
    int t = threadIdx.x;
    double s = 0.0, s2 = 0.0;
    for (int i = t; i < 1024; i += 256) { s += (double)g_part[i]; s2 += (double)g_part[1024+i]; }
    sh1[t] = s; sh2[t] = s2;
    __syncthreads();
    for (int o = 128; o; o >>= 1) {
        if (t < o) { sh1[t] += sh1[t+o]; sh2[t] += sh2[t+o]; }
        __syncthreads();
    }
    if (t == 0) {
        double n = (double)MM * (double)CC;
        double mean = sh1[0] / n;
        double var  = (sh2[0] - sh1[0]*sh1[0]/n) / (n - 1.0);
        g_ms[0] = (float)mean;
        g_ms[1] = (float)(1.0 / sqrt(var));
    }
}

// ---------------- QKV GEMM: 128x128 tile, f32x2 accumulators ----------------
__global__ void __launch_bounds__(256, 2)
qkv_gemm_kern(const float* __restrict__ X, const float* __restrict__ W) {
    __shared__ float As[16][136];   // [k][m], stride 136 -> conflict-free transpose stores
    __shared__ float Bs[16][136];   // [k][n]
    float mean = g_ms[0], istd = g_ms[1];
    int mb = blockIdx.x;            // 0..287
    int nb = blockIdx.y;            // 0..9
    int t = threadIdx.x;
    int tx = t & 15, ty = t >> 4;
    int lrow = t >> 2;              // 0..63
    int lk4  = (t & 3) * 4;         // 0,4,8,12

    const float* Xp = X + (size_t)(mb*128 + lrow)*CC + lk4;
    const float* Wp = W + (size_t)(nb*128 + lrow)*CC + lk4;

    u64 acc[8][4];
    #pragma unroll
    for (int i = 0; i < 8; i++)
        #pragma unroll
        for (int j = 0; j < 4; j++) acc[i][j] = 0ull;

    for (int k0 = 0; k0 < CC; k0 += 16) {
        float4 xa0 = *(const float4*)(Xp + k0);
        float4 xa1 = *(const float4*)(Xp + 64*CC + k0);
        float4 wb0 = *(const float4*)(Wp + k0);
        float4 wb1 = *(const float4*)(Wp + 64*CC + k0);
        __syncthreads();
        As[lk4+0][lrow] = (xa0.x - mean)*istd;
        As[lk4+1][lrow] = (xa0.y - mean)*istd;
        As[lk4+2][lrow] = (xa0.z - mean)*istd;
        As[lk4+3][lrow] = (xa0.w - mean)*istd;
        As[lk4+0][lrow+64] = (xa1.x - mean)*istd;
        As[lk4+1][lrow+64] = (xa1.y - mean)*istd;
        As[lk4+2][lrow+64] = (xa1.z - mean)*istd;
        As[lk4+3][lrow+64] = (xa1.w - mean)*istd;
        Bs[lk4+0][lrow] = wb0.x;
        Bs[lk4+1][lrow] = wb0.y;
        Bs[lk4+2][lrow] = wb0.z;
        Bs[lk4+3][lrow] = wb0.w;
        Bs[lk4+0][lrow+64] = wb1.x;
        Bs[lk4+1][lrow+64] = wb1.y;
        Bs[lk4+2][lrow+64] = wb1.z;
        Bs[lk4+3][lrow+64] = wb1.w;
        __syncthreads();
        #pragma unroll
        for (int k = 0; k < 16; k++) {
            float4 av0 = *(const float4*)&As[k][ty*8];
            float4 av1 = *(const float4*)&As[k][ty*8 + 4];
            u64 b2[4];
            b2[0] = *(const u64*)&Bs[k][tx*8];
            b2[1] = *(const u64*)&Bs[k][tx*8 + 2];
            b2[2] = *(const u64*)&Bs[k][tx*8 + 4];
            b2[3] = *(const u64*)&Bs[k][tx*8 + 6];
            u64 a2[8];
            a2[0] = dup2(av0.x); a2[1] = dup2(av0.y);
            a2[2] = dup2(av0.z); a2[3] = dup2(av0.w);
            a2[4] = dup2(av1.x); a2[5] = dup2(av1.y);
            a2[6] = dup2(av1.z); a2[7] = dup2(av1.w);
            #pragma unroll
            for (int i = 0; i < 8; i++)
                #pragma unroll
                for (int j = 0; j < 4; j++)
                    fma2(acc[i][j], a2[i], b2[j]);
        }
    }
    #pragma unroll
    for (int i = 0; i < 8; i++) {
        float o0,o1,o2,o3,o4,o5,o6,o7;
        unpack2(acc[i][0], o0, o1);
        unpack2(acc[i][1], o2, o3);
        unpack2(acc[i][2], o4, o5);
        unpack2(acc[i][3], o6, o7);
        size_t base = (size_t)(mb*128 + ty*8 + i)*FIVEC + nb*128 + tx*8;
        *(float4*)&g_qkv[base]     = make_float4(o0,o1,o2,o3);
        *(float4*)&g_qkv[base + 4] = make_float4(o4,o5,o6,o7);
    }
}

// ---------------- S1: per (b,h,i) CTA, S1[j,p] = Q_i[j,:]·K1_i[p,:] ----------------
__global__ void __launch_bounds__(256)
s1_kern() {
    __shared__ float Qs[96*36];     // [j][d], stride 36 (float4-aligned rows)
    __shared__ float Kt[32*102];    // [d][p], stride 102 (b64-aligned rows)
    int bhi = blockIdx.x;
    int i = bhi % NT;
    int bh = bhi / NT;
    int h = bh % HH, b = bh / HH;
    int baseQ = (b*NN + i*NT)*FIVEC + h*DD;
    int baseK = baseQ + CC;
    int t = threadIdx.x;
    for (int idx = t; idx < 96*32; idx += 256) {
        int r = idx >> 5, d = idx & 31;
        Qs[r*36 + d] = g_qkv[baseQ + r*FIVEC + d];
        Kt[d*102 + r] = g_qkv[baseK + r*FIVEC + d];
    }
    __syncthreads();
    int tx = t & 15, ty = t >> 4;
    int p0 = tx*6;
    u64 acc[6][3];
    #pragma unroll
    for (int r = 0; r < 6; r++)
        #pragma unroll
        for (int c = 0; c < 3; c++) acc[r][c] = 0ull;
    #pragma unroll
    for (int d0 = 0; d0 < 32; d0 += 4) {
        float a[6][4];
        #pragma unroll
        for (int r = 0; r < 6; r++)
            *(float4*)a[r] = *(const float4*)&Qs[(ty + 16*r)*36 + d0];
        #pragma unroll
        for (int dd = 0; dd < 4; dd++) {
            u64 b2[3];
            #pragma unroll
            for (int c = 0; c < 3; c++)
                b2[c] = *(const u64*)&Kt[(d0+dd)*102 + p0 + 2*c];
            #pragma unroll
            for (int r = 0; r < 6; r++) {
                u64 a2 = dup2(a[r][dd]);
                #pragma unroll
                for (int c = 0; c < 3; c++) fma2(acc[r][c], a2, b2[c]);
            }
        }
    }
    size_t base = (size_t)(bh*NT + i) * NN;
    #pragma unroll
    for (int r = 0; r < 6; r++) {
        int j = ty + 16*r;
        #pragma unroll
        for (int c = 0; c < 3; c++) {
            float lo, hi; unpack2(acc[r][c], lo, hi);
            *(float2*)&g_S[base + j*NT + p0 + 2*c] = make_float2(lo, hi);
        }
    }
}

// ---------------- S2 + softmax + O2: per (b,h,j) CTA ----------------
// dyn smem: Qs[96*36] + KV[3264] + Ss[96*98] = 64512 bytes
__global__ void __launch_bounds__(256)
s2_soft_o2_kern(float* __restrict__ Xout) {
    extern __shared__ float sm[];
    float* Qs = sm;                  // [i][d] stride 36
    float* KV = sm + 96*36;          // first Kt[d][p] stride 102, later Vs[p][d] stride 34
    float* Ss = KV + 3264;           // [i][p] stride 98
    int bhj = blockIdx.x;
    int j = bhj % NT;
    int bh = bhj / NT;
    int h = bh % HH, b = bh / HH;
    int t = threadIdx.x;
    int baseQ = (b*NN + j)*FIVEC + h*DD;
    int baseK2 = baseQ + 2*CC;
    for (int idx = t; idx < 96*32; idx += 256) {
        int r = idx >> 5, d = idx & 31;
        Qs[r*36 + d] = g_qkv[baseQ  + r*NT*FIVEC + d];
        KV[d*102 + r] = g_qkv[baseK2 + r*NT*FIVEC + d];
    }
    __syncthreads();
    int tx = t & 15, ty = t >> 4;
    size_t sBase = (size_t)bh * NT * NN + (size_t)j * NT;   // + i*NN + p
    {
        int p0 = tx*6;
        u64 acc[6][3];
        #pragma unroll
        for (int r = 0; r < 6; r++)
            #pragma unroll
            for (int c = 0; c < 3; c++) acc[r][c] = 0ull;
        #pragma unroll
        for (int d0 = 0; d0 < 32; d0 += 4) {
            float a[6][4];
            #pragma unroll
            for (int r = 0; r < 6; r++)
                *(float4*)a[r] = *(const float4*)&Qs[(ty + 16*r)*36 + d0];
            #pragma unroll
            for (int dd = 0; dd < 4; dd++) {
                u64 b2[3];
                #pragma unroll
                for (int c = 0; c < 3; c++)
                    b2[c] = *(const u64*)&KV[(d0+dd)*102 + p0 + 2*c];
                #pragma unroll
                for (int r = 0; r < 6; r++) {
                    u64 a2 = dup2(a[r][dd]);
                    #pragma unroll
                    for (int c = 0; c < 3; c++) fma2(acc[r][c], a2, b2[c]);
                }
            }
        }
        u64 scl = dup2(SCALE_L2E);
        #pragma unroll
        for (int r = 0; r < 6; r++) {
            int i = ty + 16*r;
            #pragma unroll
            for (int c = 0; c < 3; c++) {
                u64 s1v = *(const u64*)&g_S[sBase + (size_t)i*NN + p0 + 2*c];
                u64 sv = mul2(add2(acc[r][c], s1v), scl);
                float lo, hi; unpack2(sv, lo, hi);
                Ss[i*98 + p0 + 2*c]     = lo;
                Ss[i*98 + p0 + 2*c + 1] = hi;
            }
        }
    }
    __syncthreads();
    // softmax per row (base-2 domain), write A back to g_S for the O1 pass
    int warp = t >> 5, lane = t & 31;
    for (int i = warp; i < 96; i += 8) {
        float v0 = Ss[i*98 + lane];
        float v1 = Ss[i*98 + 32 + lane];
        float v2 = Ss[i*98 + 64 + lane];
        float mx = fmaxf(v0, fmaxf(v1, v2));
        #pragma unroll
        for (int o = 16; o; o >>= 1) mx = fmaxf(mx, __shfl_xor_sync(0xffffffffu, mx, o));
        v0 = ex2f(v0 - mx); v1 = ex2f(v1 - mx); v2 = ex2f(v2 - mx);
        float s = v0 + v1 + v2;
        #pragma unroll
        for (int o = 16; o; o >>= 1) s += __shfl_xor_sync(0xffffffffu, s, o);
        float inv = 1.f / s;
        v0 *= inv; v1 *= inv; v2 *= inv;
        Ss[i*98 + lane] = v0;
        Ss[i*98 + 32 + lane] = v1;
        Ss[i*98 + 64 + lane] = v2;
        g_S[sBase + (size_t)i*NN + lane]      = v0;
        g_S[sBase + (size_t)i*NN + 32 + lane] = v1;
        g_S[sBase + (size_t)i*NN + 64 + lane] = v2;
    }
    __syncthreads();
    // reload KV with V2_j as [p][d] stride 34
    for (int idx = t; idx < 96*32; idx += 256) {
        int r = idx >> 5, d = idx & 31;
        KV[r*34 + d] = g_qkv[baseQ + 4*CC + r*NT*FIVEC + d];
    }
    __syncthreads();
    // O2[i][d] = sum_p A[i][p] * V2[p][d]
    int d2 = t & 15, i0 = t >> 4;
    u64 acc2[6];
    #pragma unroll
    for (int m = 0; m < 6; m++) acc2[m] = 0ull;
    #pragma unroll 4
    for (int p = 0; p < 96; p += 2) {
        u64 vv0 = *(const u64*)&KV[p*34 + 2*d2];
        u64 vv1 = *(const u64*)&KV[(p+1)*34 + 2*d2];
        #pragma unroll
        for (int m = 0; m < 6; m++) {
            float2 a = *(const float2*)&Ss[(i0 + 16*m)*98 + p];
            fma2(acc2[m], dup2(a.x), vv0);
            fma2(acc2[m], dup2(a.y), vv1);
        }
    }
    #pragma unroll
    for (int m = 0; m < 6; m++) {
        int i = i0 + 16*m;
        float lo, hi; unpack2(acc2[m], lo, hi);
        size_t o0 = (size_t)(b*NN + i*NT + j)*CC + h*DD + 2*d2;
        *(float2*)&Xout[o0] = make_float2(lo, hi);
    }
}

// ---------------- O1 accumulate: per (b,h,i) CTA ----------------
// dyn smem: As[96*98] + Vs[96*34] = 50688 bytes
__global__ void __launch_bounds__(256)
o1_kern(float* __restrict__ Xout) {
    extern __shared__ float sm[];
    float* As = sm;                  // [j][p] stride 98
    float* Vs = sm + 96*98;          // [p][d] stride 34
    int bhi = blockIdx.x;
    int i = bhi % NT;
    int bh = bhi / NT;
    int h = bh % HH, b = bh / HH;
    int t = threadIdx.x;
    size_t aBase = (size_t)(bh*NT + i) * NN;
    for (int idx = t; idx < 96*96; idx += 256) {
        int r = idx / 96, p = idx % 96;
        As[r*98 + p] = g_S[aBase + idx];
    }
    int baseV = (b*NN + i*NT)*FIVEC + 3*CC + h*DD;
    for (int idx = t; idx < 96*32; idx += 256) {
        int r = idx >> 5, d = idx & 31;
        Vs[r*34 + d] = g_qkv[baseV + r*FIVEC + d];
    }
    __syncthreads();
    int d2 = t & 15, j0 = t >> 4;
    u64 acc2[6];
    #pragma unroll
    for (int m = 0; m < 6; m++) acc2[m] = 0ull;
    #pragma unroll 4
    for (int p = 0; p < 96; p += 2) {
        u64 vv0 = *(const u64*)&Vs[p*34 + 2*d2];
        u64 vv1 = *(const u64*)&Vs[(p+1)*34 + 2*d2];
        #pragma unroll
        for (int m = 0; m < 6; m++) {
            float2 a = *(const float2*)&As[(j0 + 16*m)*98 + p];
            fma2(acc2[m], dup2(a.x), vv0);
            fma2(acc2[m], dup2(a.y), vv1);
        }
    }
    #pragma unroll
    for (int m = 0; m < 6; m++) {
        int j = j0 + 16*m;
        size_t o0 = (size_t)(b*NN + i*NT + j)*CC + h*DD + 2*d2;
        float2 old = *(const float2*)&Xout[o0];
        float lo, hi; unpack2(acc2[m], lo, hi);
        *(float2*)&Xout[o0] = make_float2(old.x + lo, old.y + hi);
    }
}

// ---------------- pooling + head ----------------
__global__ void pool1_kern(const float* __restrict__ X) {
    int bi = blockIdx.x;
    int b = bi / NT, i = bi % NT;
    int c = threadIdx.x;
    float s = 0.f;
    for (int j = 0; j < NT; j++)
        s += X[(size_t)(b*NN + i*NT + j)*CC + c];
    g_pool[bi*CC + c] = s;
}

__global__ void pool2_head_kern(const float* __restrict__ W,
                                const float* __restrict__ bias,
                                float* __restrict__ out) {
    int b = blockIdx.x;
    __shared__ float xb[CC];
    int c = threadIdx.x;
    float s = 0.f;
    for (int i = 0; i < NT; i++)
        s += g_pool[(b*NT + i)*CC + c];
    xb[c] = s * (1.f / (float)NN);
    __syncthreads();
    float acc = bias[c];
    #pragma unroll 8
    for (int ci = 0; ci < CC; ci++)
        acc += xb[ci] * W[c*CC + ci];
    out[b*CC + c] = acc;
}

// ---------------- launch ----------------
extern "C" void kernel_launch(void* const* d_in, const int* in_sizes, int n_in,
                              void* d_out, int out_size) {
    const int*   adj   = (const int*)d_in[0];
    const float* emb   = (const float*)d_in[1];
    const float* qkvw  = (const float*)d_in[2];
    const float* headw = (const float*)d_in[3];
    const float* headb = (const float*)d_in[4];
    float* out = (float*)d_out;

    float *bufA, *bufB;
    cudaGetSymbolAddress((void**)&bufA, g_bufA);
    cudaGetSymbolAddress((void**)&bufB, g_bufB);

    const int SM_S2 = (96*36 + 3264 + 96*98) * 4;   // 64512
    const int SM_O1 = (96*98 + 96*34) * 4;          // 50688
    cudaFuncSetAttribute(s2_soft_o2_kern, cudaFuncAttributeMaxDynamicSharedMemorySize, SM_S2);
    cudaFuncSetAttribute(o1_kern,         cudaFuncAttributeMaxDynamicSharedMemorySize, SM_O1);

    detect_adj_kern<<<1, 256>>>((const unsigned int*)adj, BB*NN);
    embed_kern<<<1024, 256>>>(adj, emb, bufA);

    for (int l = 0; l < DEPTH; l++) {
        float* cur = (l & 1) ? bufB : bufA;
        float* nxt = (l & 1) ? bufA : bufB;
        red1_kern<<<1024, 256>>>(cur);
        red2_kern<<<1, 256>>>();
        qkv_gemm_kern<<<dim3(MM/128, FIVEC/128), 256>>>(cur, qkvw + (size_t)l*FIVEC*CC);
        s1_kern<<<BB*HH*NT, 256>>>();
        s2_soft_o2_kern<<<BB*HH*NT, 256, SM_S2>>>(nxt);
        o1_kern<<<BB*HH*NT, 256, SM_O1>>>(nxt);
    }
    pool1_kern<<<BB*NT, 256>>>(bufA);
    pool2_head_kern<<<BB, 256>>>(headw, headb, out);
}

// round 4
// speedup vs baseline: 2.1352x; 1.5701x over previous
#include <cuda_runtime.h>
#include <cuda_bf16.h>
#include <math.h>
#include <stdint.h>

// Problem constants
#define BB 4
#define NT 96
#define CC 256
#define HH 8
#define DD 32
#define NN (NT*NT)          // 9216
#define MM (BB*NN)          // 36864
#define FIVEC (5*CC)        // 1280
#define DEPTH 4
#define SCALE_L2E (8.83883476483184405556f * 1.44269504088896340736f)

typedef unsigned long long u64;

// ---------------- f32x2 helpers ----------------
__device__ __forceinline__ u64 dup2(float x) {
    u64 r; asm("mov.b64 %0, {%1, %1};" : "=l"(r) : "f"(x)); return r;
}
__device__ __forceinline__ void unpack2(u64 v, float& lo, float& hi) {
    asm("mov.b64 {%0, %1}, %2;" : "=f"(lo), "=f"(hi) : "l"(v));
}
__device__ __forceinline__ void fma2(u64& d, u64 a, u64 b) {
    asm("fma.rn.f32x2 %0, %1, %2, %0;" : "+l"(d) : "l"(a), "l"(b));
}
__device__ __forceinline__ u64 add2(u64 a, u64 b) {
    u64 r; asm("add.rn.f32x2 %0, %1, %2;" : "=l"(r) : "l"(a), "l"(b)); return r;
}
__device__ __forceinline__ u64 mul2(u64 a, u64 b) {
    u64 r; asm("mul.rn.f32x2 %0, %1, %2;" : "=l"(r) : "l"(a), "l"(b)); return r;
}
__device__ __forceinline__ float ex2f(float x) {
    float r; asm("ex2.approx.ftz.f32 %0, %1;" : "=f"(r) : "f"(x)); return r;
}

// ---------------- base-ISA tensor helpers (sm_80+: ldmatrix / mma.sync / cp.async) ----------------
__device__ __forceinline__ uint32_t smem_u32(const void* p) {
    uint32_t a;
    asm("{ .reg .u64 t; cvta.to.shared.u64 t, %1; cvt.u32.u64 %0, t; }" : "=r"(a) : "l"(p));
    return a;
}
__device__ __forceinline__ void cp_async16(uint32_t saddr, const void* gaddr) {
    asm volatile("cp.async.cg.shared.global [%0], [%1], 16;" :: "r"(saddr), "l"(gaddr));
}
__device__ __forceinline__ void cp_commit() {
    asm volatile("cp.async.commit_group;" ::: "memory");
}
template <int N>
__device__ __forceinline__ void cp_wait() {
    asm volatile("cp.async.wait_group %0;" :: "n"(N) : "memory");
}
__device__ __forceinline__ void ldsm_x4(uint32_t* r, uint32_t addr) {
    asm volatile("ldmatrix.sync.aligned.m8n8.x4.shared.b16 {%0,%1,%2,%3}, [%4];"
                 : "=r"(r[0]), "=r"(r[1]), "=r"(r[2]), "=r"(r[3]) : "r"(addr));
}
__device__ __forceinline__ void ldsm_x2(uint32_t* r, uint32_t addr) {
    asm volatile("ldmatrix.sync.aligned.m8n8.x2.shared.b16 {%0,%1}, [%2];"
                 : "=r"(r[0]), "=r"(r[1]) : "r"(addr));
}
__device__ __forceinline__ void mma16816(float* d, const uint32_t* a, const uint32_t* b) {
    asm volatile(
        "mma.sync.aligned.m16n8k16.row.col.f32.bf16.bf16.f32 "
        "{%0,%1,%2,%3}, {%4,%5,%6,%7}, {%8,%9}, {%0,%1,%2,%3};"
        : "+f"(d[0]), "+f"(d[1]), "+f"(d[2]), "+f"(d[3])
        : "r"(a[0]), "r"(a[1]), "r"(a[2]), "r"(a[3]), "r"(b[0]), "r"(b[1]));
}
__device__ __forceinline__ uint32_t sw128(uint32_t off) {
    return off ^ ((off >> 3) & 0x70);
}

// ---------------- device global scratch ----------------
__device__ float g_bufA[MM*CC];
__device__ float g_bufB[MM*CC];
__device__ float g_qkv[MM*FIVEC];
__device__ float g_S[BB*HH*NT*NN];              // [b,h,i,j,p]
__device__ float g_part[2*1024];
__device__ float g_ms[2];
__device__ float g_pool[BB*NT*CC];
__device__ int   g_isI64;
// bf16 split operands, pre-swizzled SW128 tile layout
// X: [mtile 0..287][kchunk 0..3][128 rows x 64 bf16 = 16KB = 1024 uint4]
__device__ uint4 g_xhi[288*4*1024];
__device__ uint4 g_xlo[288*4*1024];
// W: [layer][ntile 0..9][kchunk 0..3][128 rows x 64 bf16 = 16KB = 1024 uint4]
__device__ uint4 g_whi[DEPTH*10*4*1024];
__device__ uint4 g_wlo[DEPTH*10*4*1024];

// ---------------- adj dtype detection ----------------
__global__ void detect_adj_kern(const unsigned int* __restrict__ a, int n) {
    __shared__ int any;
    if (threadIdx.x == 0) any = 0;
    __syncthreads();
    int nz = 0;
    for (int i = 1 + 2*threadIdx.x; i < n; i += 2*blockDim.x)
        nz |= (a[i] != 0u);
    if (nz) any = 1;
    __syncthreads();
    if (threadIdx.x == 0) g_isI64 = any ? 0 : 1;
}

// ---------------- embedding gather ----------------
__global__ void embed_kern(const int* __restrict__ adj,
                           const float* __restrict__ emb,
                           float* __restrict__ X) {
    int i64 = g_isI64;
    int total = MM * (CC/4);
    for (int t = blockIdx.x*blockDim.x + threadIdx.x; t < total;
         t += gridDim.x*blockDim.x) {
        int m = t >> 6;
        int c4 = t & 63;
        int a = i64 ? adj[2*m] : adj[m];
        float4 v = ((const float4*)emb)[a*(CC/4) + c4];
        ((float4*)X)[m*(CC/4) + c4] = v;
    }
}

// ---------------- global mean/std reduction ----------------
__global__ void red1_kern(const float* __restrict__ X) {
    float s = 0.f, s2 = 0.f;
    for (int i = blockIdx.x*blockDim.x + threadIdx.x; i < MM*CC;
         i += gridDim.x*blockDim.x) {
        float v = X[i];
        s += v; s2 += v*v;
    }
    __shared__ float sh1[256], sh2[256];
    int t = threadIdx.x;
    sh1[t] = s; sh2[t] = s2;
    __syncthreads();
    for (int o = 128; o; o >>= 1) {
        if (t < o) { sh1[t] += sh1[t+o]; sh2[t] += sh2[t+o]; }
        __syncthreads();
    }
    if (t == 0) { g_part[blockIdx.x] = sh1[0]; g_part[1024 + blockIdx.x] = sh2[0]; }
}

__global__ void red2_kern() {
    __shared__ double sh1[256], sh2[256];
    int t = threadIdx.x;
    double s = 0.0, s2 = 0.0;
    for (int i = t; i < 1024; i += 256) { s += (double)g_part[i]; s2 += (double)g_part[1024+i]; }
    sh1[t] = s; sh2[t] = s2;
    __syncthreads();
    for (int o = 128; o; o >>= 1) {
        if (t < o) { sh1[t] += sh1[t+o]; sh2[t] += sh2[t+o]; }
        __syncthreads();
    }
    if (t == 0) {
        double n = (double)MM * (double)CC;
        double mean = sh1[0] / n;
        double var  = (sh2[0] - sh1[0]*sh1[0]/n) / (n - 1.0);
        g_ms[0] = (float)mean;
        g_ms[1] = (float)(1.0 / sqrt(var));
    }
}

// ---------------- bf16 split conversions (pre-swizzled SW128 tile layout) ----------------
__device__ __forceinline__ uint32_t pack_bf2(__nv_bfloat16 a, __nv_bfloat16 b) {
    return (uint32_t)__bfloat16_as_ushort(a) | ((uint32_t)__bfloat16_as_ushort(b) << 16);
}

// X: fused norm + hi/lo split.  idx over MM*32 (each thread: 8 k's = 16B chunk)
__global__ void convert_x_kern(const float* __restrict__ X) {
    int idx = blockIdx.x*blockDim.x + threadIdx.x;
    if (idx >= MM*32) return;
    float mean = g_ms[0], istd = g_ms[1];
    int m = idx >> 5, k8 = idx & 31;
    const float4* src = (const float4*)(X + (size_t)m*CC + k8*8);
    float4 v0 = src[0], v1 = src[1];
    float v[8] = {v0.x,v0.y,v0.z,v0.w,v1.x,v1.y,v1.z,v1.w};
    uint32_t hw[4], lw[4];
    #pragma unroll
    for (int j = 0; j < 4; j++) {
        float a0 = (v[2*j]   - mean)*istd;
        float a1 = (v[2*j+1] - mean)*istd;
        __nv_bfloat16 h0 = __float2bfloat16(a0), h1 = __float2bfloat16(a1);
        __nv_bfloat16 l0 = __float2bfloat16(a0 - __bfloat162float(h0));
        __nv_bfloat16 l1 = __float2bfloat16(a1 - __bfloat162float(h1));
        hw[j] = pack_bf2(h0, h1);
        lw[j] = pack_bf2(l0, l1);
    }
    int mt = m >> 7, r = m & 127, kc = k8 >> 3;
    uint32_t off = r*128 + (k8 & 7)*16;
    uint32_t sw = sw128(off);
    size_t tile = (size_t)(mt*4 + kc)*1024 + (sw >> 4);
    g_xhi[tile] = make_uint4(hw[0], hw[1], hw[2], hw[3]);
    g_xlo[tile] = make_uint4(lw[0], lw[1], lw[2], lw[3]);
}

// W: all layers, once per call. idx over DEPTH*1280*32
__global__ void convert_w_kern(const float* __restrict__ W) {
    int idx = blockIdx.x*blockDim.x + threadIdx.x;
    if (idx >= DEPTH*FIVEC*32) return;
    int l = idx / (FIVEC*32);
    int rem = idx % (FIVEC*32);
    int n = rem >> 5, k8 = rem & 31;
    const float4* src = (const float4*)(W + (size_t)l*FIVEC*CC + (size_t)n*CC + k8*8);
    float4 v0 = src[0], v1 = src[1];
    float v[8] = {v0.x,v0.y,v0.z,v0.w,v1.x,v1.y,v1.z,v1.w};
    uint32_t hw[4], lw[4];
    #pragma unroll
    for (int j = 0; j < 4; j++) {
        __nv_bfloat16 h0 = __float2bfloat16(v[2*j]),   h1 = __float2bfloat16(v[2*j+1]);
        __nv_bfloat16 l0 = __float2bfloat16(v[2*j]   - __bfloat162float(h0));
        __nv_bfloat16 l1 = __float2bfloat16(v[2*j+1] - __bfloat162float(h1));
        hw[j] = pack_bf2(h0, h1);
        lw[j] = pack_bf2(l0, l1);
    }
    int nt = n >> 7, r = n & 127, kc = k8 >> 3;
    uint32_t off = r*128 + (k8 & 7)*16;
    uint32_t sw = sw128(off);
    size_t tile = (size_t)((l*10 + nt)*4 + kc)*1024 + (sw >> 4);
    g_whi[tile] = make_uint4(hw[0], hw[1], hw[2], hw[3]);
    g_wlo[tile] = make_uint4(lw[0], lw[1], lw[2], lw[3]);
}

// ---------------- QKV GEMM via mma.sync bf16: D[128,128] per CTA, K = 12 chunks of 64 ----------------
// dyn smem: 2 stages x (A 16KB + B 16KB) = 65536 bytes
#define SM_QKV 65536
__global__ void __launch_bounds__(256, 2)
qkv_mma_kern(int layer) {
    extern __shared__ char smem[];
    uint32_t sb = smem_u32(smem);
    int t = threadIdx.x, lane = t & 31, wid = t >> 5;
    int mt = blockIdx.x, ntile = blockIdx.y;
    int wm = wid & 1, wn = wid >> 1;

    float acc[4][4][4];
    #pragma unroll
    for (int a = 0; a < 4; a++)
        #pragma unroll
        for (int b = 0; b < 4; b++)
            #pragma unroll
            for (int c = 0; c < 4; c++) acc[a][b][c] = 0.f;

    // chunk c: A from xhi(c<4 or c>=8) / xlo(4..7) kchunk akc; B from whi(c<8)/wlo kchunk bkc
    auto issue_copy = [&](int c) {
        int s = c & 1;
        int akc = (c < 4) ? c : ((c < 8) ? c - 4 : c - 8);
        const uint4* Ap = ((c >= 4 && c < 8) ? g_xlo : g_xhi) + (size_t)(mt*4 + akc)*1024;
        int bkc = (c < 8) ? (c & 3) : (c - 8);
        const uint4* Bp = ((c < 8) ? g_whi : g_wlo) + (size_t)((layer*10 + ntile)*4 + bkc)*1024;
        uint32_t sa = sb + s*32768;
        #pragma unroll
        for (int i = 0; i < 4; i++)
            cp_async16(sa + (t + i*256)*16, Ap + t + i*256);
        uint32_t sbB = sa + 16384;
        #pragma unroll
        for (int i = 0; i < 4; i++)
            cp_async16(sbB + (t + i*256)*16, Bp + t + i*256);
        cp_commit();
    };

    issue_copy(0);
    #pragma unroll 1
    for (int c = 0; c < 12; c++) {
        int s = c & 1;
        if (c < 11) { issue_copy(c + 1); cp_wait<1>(); }
        else        { cp_wait<0>(); }
        __syncthreads();
        uint32_t Ab = sb + s*32768;
        uint32_t Bb = Ab + 16384;
        #pragma unroll
        for (int ks = 0; ks < 4; ks++) {
            uint32_t afr[4][4];
            #pragma unroll
            for (int mf = 0; mf < 4; mf++) {
                uint32_t off = (uint32_t)(wm*64 + mf*16 + (lane & 15))*128
                             + ks*32 + (lane >> 4)*16;
                ldsm_x4(afr[mf], Ab + sw128(off));
            }
            uint32_t bfr[4][2];
            #pragma unroll
            for (int nf = 0; nf < 4; nf++) {
                uint32_t off = (uint32_t)(wn*32 + nf*8 + (lane & 7))*128
                             + ks*32 + ((lane >> 3) & 1)*16;
                ldsm_x2(bfr[nf], Bb + sw128(off));
            }
            #pragma unroll
            for (int mf = 0; mf < 4; mf++)
                #pragma unroll
                for (int nf = 0; nf < 4; nf++)
                    mma16816(acc[mf][nf], afr[mf], bfr[nf]);
        }
        __syncthreads();
    }
    // epilogue: thread t of warp holds rows (lane>>2), (lane>>2)+8; cols 2*(lane&3),+1
    int rbase = mt*128 + wm*64 + (lane >> 2);
    int cbase = ntile*128 + wn*32 + (lane & 3)*2;
    #pragma unroll
    for (int mf = 0; mf < 4; mf++) {
        #pragma unroll
        for (int nf = 0; nf < 4; nf++) {
            size_t o0 = (size_t)(rbase + mf*16)*FIVEC + cbase + nf*8;
            *(float2*)&g_qkv[o0]              = make_float2(acc[mf][nf][0], acc[mf][nf][1]);
            *(float2*)&g_qkv[o0 + 8*FIVEC]    = make_float2(acc[mf][nf][2], acc[mf][nf][3]);
        }
    }
}

// ---------------- S1: per (b,h,i) CTA, S1[j,p] = Q_i[j,:]·K1_i[p,:] ----------------
__global__ void __launch_bounds__(256)
s1_kern() {
    __shared__ float Qs[96*36];
    __shared__ float Kt[32*102];
    int bhi = blockIdx.x;
    int i = bhi % NT;
    int bh = bhi / NT;
    int h = bh % HH, b = bh / HH;
    int baseQ = (b*NN + i*NT)*FIVEC + h*DD;
    int baseK = baseQ + CC;
    int t = threadIdx.x;
    for (int idx = t; idx < 96*32; idx += 256) {
        int r = idx >> 5, d = idx & 31;
        Qs[r*36 + d] = g_qkv[baseQ + r*FIVEC + d];
        Kt[d*102 + r] = g_qkv[baseK + r*FIVEC + d];
    }
    __syncthreads();
    int tx = t & 15, ty = t >> 4;
    int p0 = tx*6;
    u64 acc[6][3];
    #pragma unroll
    for (int r = 0; r < 6; r++)
        #pragma unroll
        for (int c = 0; c < 3; c++) acc[r][c] = 0ull;
    #pragma unroll
    for (int d0 = 0; d0 < 32; d0 += 4) {
        float a[6][4];
        #pragma unroll
        for (int r = 0; r < 6; r++)
            *(float4*)a[r] = *(const float4*)&Qs[(ty + 16*r)*36 + d0];
        #pragma unroll
        for (int dd = 0; dd < 4; dd++) {
            u64 b2[3];
            #pragma unroll
            for (int c = 0; c < 3; c++)
                b2[c] = *(const u64*)&Kt[(d0+dd)*102 + p0 + 2*c];
            #pragma unroll
            for (int r = 0; r < 6; r++) {
                u64 a2 = dup2(a[r][dd]);
                #pragma unroll
                for (int c = 0; c < 3; c++) fma2(acc[r][c], a2, b2[c]);
            }
        }
    }
    size_t base = (size_t)(bh*NT + i) * NN;
    #pragma unroll
    for (int r = 0; r < 6; r++) {
        int j = ty + 16*r;
        #pragma unroll
        for (int c = 0; c < 3; c++) {
            float lo, hi; unpack2(acc[r][c], lo, hi);
            *(float2*)&g_S[base + j*NT + p0 + 2*c] = make_float2(lo, hi);
        }
    }
}

// ---------------- S2 + softmax + O2: per (b,h,j) CTA ----------------
__global__ void __launch_bounds__(256)
s2_soft_o2_kern(float* __restrict__ Xout) {
    extern __shared__ float sm[];
    float* Qs = sm;
    float* KV = sm + 96*36;
    float* Ss = KV + 3264;
    int bhj = blockIdx.x;
    int j = bhj % NT;
    int bh = bhj / NT;
    int h = bh % HH, b = bh / HH;
    int t = threadIdx.x;
    int baseQ = (b*NN + j)*FIVEC + h*DD;
    int baseK2 = baseQ + 2*CC;
    for (int idx = t; idx < 96*32; idx += 256) {
        int r = idx >> 5, d = idx & 31;
        Qs[r*36 + d] = g_qkv[baseQ  + r*NT*FIVEC + d];
        KV[d*102 + r] = g_qkv[baseK2 + r*NT*FIVEC + d];
    }
    __syncthreads();
    int tx = t & 15, ty = t >> 4;
    size_t sBase = (size_t)bh * NT * NN + (size_t)j * NT;
    {
        int p0 = tx*6;
        u64 acc[6][3];
        #pragma unroll
        for (int r = 0; r < 6; r++)
            #pragma unroll
            for (int c = 0; c < 3; c++) acc[r][c] = 0ull;
        #pragma unroll
        for (int d0 = 0; d0 < 32; d0 += 4) {
            float a[6][4];
            #pragma unroll
            for (int r = 0; r < 6; r++)
                *(float4*)a[r] = *(const float4*)&Qs[(ty + 16*r)*36 + d0];
            #pragma unroll
            for (int dd = 0; dd < 4; dd++) {
                u64 b2[3];
                #pragma unroll
                for (int c = 0; c < 3; c++)
                    b2[c] = *(const u64*)&KV[(d0+dd)*102 + p0 + 2*c];
                #pragma unroll
                for (int r = 0; r < 6; r++) {
                    u64 a2 = dup2(a[r][dd]);
                    #pragma unroll
                    for (int c = 0; c < 3; c++) fma2(acc[r][c], a2, b2[c]);
                }
            }
        }
        u64 scl = dup2(SCALE_L2E);
        #pragma unroll
        for (int r = 0; r < 6; r++) {
            int i = ty + 16*r;
            #pragma unroll
            for (int c = 0; c < 3; c++) {
                u64 s1v = *(const u64*)&g_S[sBase + (size_t)i*NN + p0 + 2*c];
                u64 sv = mul2(add2(acc[r][c], s1v), scl);
                float lo, hi; unpack2(sv, lo, hi);
                Ss[i*98 + p0 + 2*c]     = lo;
                Ss[i*98 + p0 + 2*c + 1] = hi;
            }
        }
    }
    __syncthreads();
    int warp = t >> 5, lane = t & 31;
    for (int i = warp; i < 96; i += 8) {
        float v0 = Ss[i*98 + lane];
        float v1 = Ss[i*98 + 32 + lane];
        float v2 = Ss[i*98 + 64 + lane];
        float mx = fmaxf(v0, fmaxf(v1, v2));
        #pragma unroll
        for (int o = 16; o; o >>= 1) mx = fmaxf(mx, __shfl_xor_sync(0xffffffffu, mx, o));
        v0 = ex2f(v0 - mx); v1 = ex2f(v1 - mx); v2 = ex2f(v2 - mx);
        float s = v0 + v1 + v2;
        #pragma unroll
        for (int o = 16; o; o >>= 1) s += __shfl_xor_sync(0xffffffffu, s, o);
        float inv = 1.f / s;
        v0 *= inv; v1 *= inv; v2 *= inv;
        Ss[i*98 + lane] = v0;
        Ss[i*98 + 32 + lane] = v1;
        Ss[i*98 + 64 + lane] = v2;
        g_S[sBase + (size_t)i*NN + lane]      = v0;
        g_S[sBase + (size_t)i*NN + 32 + lane] = v1;
        g_S[sBase + (size_t)i*NN + 64 + lane] = v2;
    }
    __syncthreads();
    for (int idx = t; idx < 96*32; idx += 256) {
        int r = idx >> 5, d = idx & 31;
        KV[r*34 + d] = g_qkv[baseQ + 4*CC + r*NT*FIVEC + d];
    }
    __syncthreads();
    int d2 = t & 15, i0 = t >> 4;
    u64 acc2[6];
    #pragma unroll
    for (int m = 0; m < 6; m++) acc2[m] = 0ull;
    #pragma unroll 4
    for (int p = 0; p < 96; p += 2) {
        u64 vv0 = *(const u64*)&KV[p*34 + 2*d2];
        u64 vv1 = *(const u64*)&KV[(p+1)*34 + 2*d2];
        #pragma unroll
        for (int m = 0; m < 6; m++) {
            float2 a = *(const float2*)&Ss[(i0 + 16*m)*98 + p];
            fma2(acc2[m], dup2(a.x), vv0);
            fma2(acc2[m], dup2(a.y), vv1);
        }
    }
    #pragma unroll
    for (int m = 0; m < 6; m++) {
        int i = i0 + 16*m;
        float lo, hi; unpack2(acc2[m], lo, hi);
        size_t o0 = (size_t)(b*NN + i*NT + j)*CC + h*DD + 2*d2;
        *(float2*)&Xout[o0] = make_float2(lo, hi);
    }
}

// ---------------- O1 accumulate: per (b,h,i) CTA ----------------
__global__ void __launch_bounds__(256)
o1_kern(float* __restrict__ Xout) {
    extern __shared__ float sm[];
    float* As = sm;
    float* Vs = sm + 96*98;
    int bhi = blockIdx.x;
    int i = bhi % NT;
    int bh = bhi / NT;
    int h = bh % HH, b = bh / HH;
    int t = threadIdx.x;
    size_t aBase = (size_t)(bh*NT + i) * NN;
    for (int idx = t; idx < 96*96; idx += 256) {
        int r = idx / 96, p = idx % 96;
        As[r*98 + p] = g_S[aBase + idx];
    }
    int baseV = (b*NN + i*NT)*FIVEC + 3*CC + h*DD;
    for (int idx = t; idx < 96*32; idx += 256) {
        int r = idx >> 5, d = idx & 31;
        Vs[r*34 + d] = g_qkv[baseV + r*FIVEC + d];
    }
    __syncthreads();
    int d2 = t & 15, j0 = t >> 4;
    u64 acc2[6];
    #pragma unroll
    for (int m = 0; m < 6; m++) acc2[m] = 0ull;
    #pragma unroll 4
    for (int p = 0; p < 96; p += 2) {
        u64 vv0 = *(const u64*)&Vs[p*34 + 2*d2];
        u64 vv1 = *(const u64*)&Vs[(p+1)*34 + 2*d2];
        #pragma unroll
        for (int m = 0; m < 6; m++) {
            float2 a = *(const float2*)&As[(j0 + 16*m)*98 + p];
            fma2(acc2[m], dup2(a.x), vv0);
            fma2(acc2[m], dup2(a.y), vv1);
        }
    }
    #pragma unroll
    for (int m = 0; m < 6; m++) {
        int j = j0 + 16*m;
        size_t o0 = (size_t)(b*NN + i*NT + j)*CC + h*DD + 2*d2;
        float2 old = *(const float2*)&Xout[o0];
        float lo, hi; unpack2(acc2[m], lo, hi);
        *(float2*)&Xout[o0] = make_float2(old.x + lo, old.y + hi);
    }
}

// ---------------- pooling + head ----------------
__global__ void pool1_kern(const float* __restrict__ X) {
    int bi = blockIdx.x;
    int b = bi / NT, i = bi % NT;
    int c = threadIdx.x;
    float s = 0.f;
    for (int j = 0; j < NT; j++)
        s += X[(size_t)(b*NN + i*NT + j)*CC + c];
    g_pool[bi*CC + c] = s;
}

__global__ void pool2_head_kern(const float* __restrict__ W,
                                const float* __restrict__ bias,
                                float* __restrict__ out) {
    int b = blockIdx.x;
    __shared__ float xb[CC];
    int c = threadIdx.x;
    float s = 0.f;
    for (int i = 0; i < NT; i++)
        s += g_pool[(b*NT + i)*CC + c];
    xb[c] = s * (1.f / (float)NN);
    __syncthreads();
    float acc = bias[c];
    #pragma unroll 8
    for (int ci = 0; ci < CC; ci++)
        acc += xb[ci] * W[c*CC + ci];
    out[b*CC + c] = acc;
}

// ---------------- launch ----------------
extern "C" void kernel_launch(void* const* d_in, const int* in_sizes, int n_in,
                              void* d_out, int out_size) {
    const int*   adj   = (const int*)d_in[0];
    const float* emb   = (const float*)d_in[1];
    const float* qkvw  = (const float*)d_in[2];
    const float* headw = (const float*)d_in[3];
    const float* headb = (const float*)d_in[4];
    float* out = (float*)d_out;

    float *bufA, *bufB;
    cudaGetSymbolAddress((void**)&bufA, g_bufA);
    cudaGetSymbolAddress((void**)&bufB, g_bufB);

    const int SM_S2 = (96*36 + 3264 + 96*98) * 4;   // 64512
    const int SM_O1 = (96*98 + 96*34) * 4;          // 50688
    cudaFuncSetAttribute(s2_soft_o2_kern, cudaFuncAttributeMaxDynamicSharedMemorySize, SM_S2);
    cudaFuncSetAttribute(o1_kern,         cudaFuncAttributeMaxDynamicSharedMemorySize, SM_O1);
    cudaFuncSetAttribute(qkv_mma_kern,    cudaFuncAttributeMaxDynamicSharedMemorySize, SM_QKV);

    detect_adj_kern<<<1, 256>>>((const unsigned int*)adj, BB*NN);
    embed_kern<<<1024, 256>>>(adj, emb, bufA);
    convert_w_kern<<<(DEPTH*FIVEC*32 + 255)/256, 256>>>(qkvw);

    for (int l = 0; l < DEPTH; l++) {
        float* cur = (l & 1) ? bufB : bufA;
        float* nxt = (l & 1) ? bufA : bufB;
        red1_kern<<<1024, 256>>>(cur);
        red2_kern<<<1, 256>>>();
        convert_x_kern<<<(MM*32 + 255)/256, 256>>>(cur);
        qkv_mma_kern<<<dim3(MM/128, FIVEC/128), 256, SM_QKV>>>(l);
        s1_kern<<<BB*HH*NT, 256>>>();
        s2_soft_o2_kern<<<BB*HH*NT, 256, SM_S2>>>(nxt);
        o1_kern<<<BB*HH*NT, 256, SM_O1>>>(nxt);
    }
    pool1_kern<<<BB*NT, 256>>>(bufA);
    pool2_head_kern<<<BB, 256>>>(headw, headb, out);
}

// round 5
// speedup vs baseline: 2.3798x; 1.1146x over previous
#include <cuda_runtime.h>
#include <cuda_bf16.h>
#include <math.h>
#include <stdint.h>

// Problem constants
#define BB 4
#define NT 96
#define CC 256
#define HH 8
#define DD 32
#define NN (NT*NT)          // 9216
#define MM (BB*NN)          // 36864
#define FIVEC (5*CC)        // 1280
#define DEPTH 4
#define SCALE_L2E (8.83883476483184405556f * 1.44269504088896340736f)

__device__ __forceinline__ float ex2f(float x) {
    float r; asm("ex2.approx.ftz.f32 %0, %1;" : "=f"(r) : "f"(x)); return r;
}

// ---------------- base-ISA tensor helpers (sm_80+) ----------------
__device__ __forceinline__ uint32_t smem_u32(const void* p) {
    uint32_t a;
    asm("{ .reg .u64 t; cvta.to.shared.u64 t, %1; cvt.u32.u64 %0, t; }" : "=r"(a) : "l"(p));
    return a;
}
__device__ __forceinline__ void cp_async16(uint32_t saddr, const void* gaddr) {
    asm volatile("cp.async.cg.shared.global [%0], [%1], 16;" :: "r"(saddr), "l"(gaddr));
}
__device__ __forceinline__ void cp_commit() {
    asm volatile("cp.async.commit_group;" ::: "memory");
}
template <int N>
__device__ __forceinline__ void cp_wait() {
    asm volatile("cp.async.wait_group %0;" :: "n"(N) : "memory");
}
__device__ __forceinline__ void ldsm_x4(uint32_t* r, uint32_t addr) {
    asm volatile("ldmatrix.sync.aligned.m8n8.x4.shared.b16 {%0,%1,%2,%3}, [%4];"
                 : "=r"(r[0]), "=r"(r[1]), "=r"(r[2]), "=r"(r[3]) : "r"(addr));
}
__device__ __forceinline__ void ldsm_x2(uint32_t* r, uint32_t addr) {
    asm volatile("ldmatrix.sync.aligned.m8n8.x2.shared.b16 {%0,%1}, [%2];"
                 : "=r"(r[0]), "=r"(r[1]) : "r"(addr));
}
__device__ __forceinline__ void mma16816(float* d, const uint32_t* a, const uint32_t* b) {
    asm volatile(
        "mma.sync.aligned.m16n8k16.row.col.f32.bf16.bf16.f32 "
        "{%0,%1,%2,%3}, {%4,%5,%6,%7}, {%8,%9}, {%0,%1,%2,%3};"
        : "+f"(d[0]), "+f"(d[1]), "+f"(d[2]), "+f"(d[3])
        : "r"(a[0]), "r"(a[1]), "r"(a[2]), "r"(a[3]), "r"(b[0]), "r"(b[1]));
}
__device__ __forceinline__ uint32_t sw128(uint32_t off) {
    return off ^ ((off >> 3) & 0x70);
}
__device__ __forceinline__ void sts128(uint32_t addr, uint32_t a, uint32_t b, uint32_t c, uint32_t d) {
    asm volatile("st.shared.v4.b32 [%0], {%1,%2,%3,%4};" :: "r"(addr), "r"(a), "r"(b), "r"(c), "r"(d));
}
__device__ __forceinline__ void sts32(uint32_t addr, uint32_t a) {
    asm volatile("st.shared.b32 [%0], %1;" :: "r"(addr), "r"(a));
}
__device__ __forceinline__ uint32_t pack_bf2(__nv_bfloat16 a, __nv_bfloat16 b) {
    return (uint32_t)__bfloat16_as_ushort(a) | ((uint32_t)__bfloat16_as_ushort(b) << 16);
}
__device__ __forceinline__ void split2(float a, float b, uint32_t& hi, uint32_t& lo) {
    __nv_bfloat16 h0 = __float2bfloat16(a), h1 = __float2bfloat16(b);
    __nv_bfloat16 l0 = __float2bfloat16(a - __bfloat162float(h0));
    __nv_bfloat16 l1 = __float2bfloat16(b - __bfloat162float(h1));
    hi = pack_bf2(h0, h1); lo = pack_bf2(l0, l1);
}
// load 8 floats, split hi/lo, store 16B each
__device__ __forceinline__ void cvt8(const float* src, uint32_t hiaddr, uint32_t loaddr) {
    float4 v0 = *(const float4*)src;
    float4 v1 = *(const float4*)(src + 4);
    float v[8] = {v0.x,v0.y,v0.z,v0.w,v1.x,v1.y,v1.z,v1.w};
    uint32_t hw[4], lw[4];
    #pragma unroll
    for (int jj = 0; jj < 4; jj++) split2(v[2*jj], v[2*jj+1], hw[jj], lw[jj]);
    sts128(hiaddr, hw[0], hw[1], hw[2], hw[3]);
    sts128(loaddr, lw[0], lw[1], lw[2], lw[3]);
}

// ---------------- device global scratch ----------------
__device__ float g_bufA[MM*CC];
__device__ float g_bufB[MM*CC];
__device__ float g_qkv[MM*FIVEC];
__device__ float g_S[BB*HH*NT*NN];              // [b,h,i,j,p]
__device__ float g_part[2*1024];
__device__ float g_ms[2];
__device__ float g_pool[BB*NT*CC];
__device__ int   g_isI64;
// bf16 split operands for QKV GEMM (pre-swizzled tiles, as in R4)
__device__ uint4 g_xhi[288*4*1024];
__device__ uint4 g_xlo[288*4*1024];
__device__ uint4 g_whi[DEPTH*10*4*1024];
__device__ uint4 g_wlo[DEPTH*10*4*1024];

// ---------------- adj dtype detection ----------------
__global__ void detect_adj_kern(const unsigned int* __restrict__ a, int n) {
    __shared__ int any;
    if (threadIdx.x == 0) any = 0;
    __syncthreads();
    int nz = 0;
    for (int i = 1 + 2*threadIdx.x; i < n; i += 2*blockDim.x)
        nz |= (a[i] != 0u);
    if (nz) any = 1;
    __syncthreads();
    if (threadIdx.x == 0) g_isI64 = any ? 0 : 1;
}

// ---------------- embedding gather ----------------
__global__ void embed_kern(const int* __restrict__ adj,
                           const float* __restrict__ emb,
                           float* __restrict__ X) {
    int i64 = g_isI64;
    int total = MM * (CC/4);
    for (int t = blockIdx.x*blockDim.x + threadIdx.x; t < total;
         t += gridDim.x*blockDim.x) {
        int m = t >> 6;
        int c4 = t & 63;
        int a = i64 ? adj[2*m] : adj[m];
        float4 v = ((const float4*)emb)[a*(CC/4) + c4];
        ((float4*)X)[m*(CC/4) + c4] = v;
    }
}

// ---------------- global mean/std reduction ----------------
__global__ void red1_kern(const float* __restrict__ X) {
    float s = 0.f, s2 = 0.f;
    for (int i = blockIdx.x*blockDim.x + threadIdx.x; i < MM*CC;
         i += gridDim.x*blockDim.x) {
        float v = X[i];
        s += v; s2 += v*v;
    }
    __shared__ float sh1[256], sh2[256];
    int t = threadIdx.x;
    sh1[t] = s; sh2[t] = s2;
    __syncthreads();
    for (int o = 128; o; o >>= 1) {
        if (t < o) { sh1[t] += sh1[t+o]; sh2[t] += sh2[t+o]; }
        __syncthreads();
    }
    if (t == 0) { g_part[blockIdx.x] = sh1[0]; g_part[1024 + blockIdx.x] = sh2[0]; }
}

__global__ void red2_kern() {
    __shared__ double sh1[256], sh2[256];
    int t = threadIdx.x;
    double s = 0.0, s2 = 0.0;
    for (int i = t; i < 1024; i += 256) { s += (double)g_part[i]; s2 += (double)g_part[1024+i]; }
    sh1[t] = s; sh2[t] = s2;
    __syncthreads();
    for (int o = 128; o; o >>= 1) {
        if (t < o) { sh1[t] += sh1[t+o]; sh2[t] += sh2[t+o]; }
        __syncthreads();
    }
    if (t == 0) {
        double n = (double)MM * (double)CC;
        double mean = sh1[0] / n;
        double var  = (sh2[0] - sh1[0]*sh1[0]/n) / (n - 1.0);
        g_ms[0] = (float)mean;
        g_ms[1] = (float)(1.0 / sqrt(var));
    }
}

// ---------------- bf16 split conversions for QKV (pre-swizzled tiles) ----------------
__global__ void convert_x_kern(const float* __restrict__ X) {
    int idx = blockIdx.x*blockDim.x + threadIdx.x;
    if (idx >= MM*32) return;
    float mean = g_ms[0], istd = g_ms[1];
    int m = idx >> 5, k8 = idx & 31;
    const float4* src = (const float4*)(X + (size_t)m*CC + k8*8);
    float4 v0 = src[0], v1 = src[1];
    float v[8] = {v0.x,v0.y,v0.z,v0.w,v1.x,v1.y,v1.z,v1.w};
    uint32_t hw[4], lw[4];
    #pragma unroll
    for (int j = 0; j < 4; j++)
        split2((v[2*j] - mean)*istd, (v[2*j+1] - mean)*istd, hw[j], lw[j]);
    int mt = m >> 7, r = m & 127, kc = k8 >> 3;
    uint32_t off = r*128 + (k8 & 7)*16;
    uint32_t sw = sw128(off);
    size_t tile = (size_t)(mt*4 + kc)*1024 + (sw >> 4);
    g_xhi[tile] = make_uint4(hw[0], hw[1], hw[2], hw[3]);
    g_xlo[tile] = make_uint4(lw[0], lw[1], lw[2], lw[3]);
}

__global__ void convert_w_kern(const float* __restrict__ W) {
    int idx = blockIdx.x*blockDim.x + threadIdx.x;
    if (idx >= DEPTH*FIVEC*32) return;
    int l = idx / (FIVEC*32);
    int rem = idx % (FIVEC*32);
    int n = rem >> 5, k8 = rem & 31;
    const float4* src = (const float4*)(W + (size_t)l*FIVEC*CC + (size_t)n*CC + k8*8);
    float4 v0 = src[0], v1 = src[1];
    float v[8] = {v0.x,v0.y,v0.z,v0.w,v1.x,v1.y,v1.z,v1.w};
    uint32_t hw[4], lw[4];
    #pragma unroll
    for (int j = 0; j < 4; j++)
        split2(v[2*j], v[2*j+1], hw[j], lw[j]);
    int nt = n >> 7, r = n & 127, kc = k8 >> 3;
    uint32_t off = r*128 + (k8 & 7)*16;
    uint32_t sw = sw128(off);
    size_t tile = (size_t)((l*10 + nt)*4 + kc)*1024 + (sw >> 4);
    g_whi[tile] = make_uint4(hw[0], hw[1], hw[2], hw[3]);
    g_wlo[tile] = make_uint4(lw[0], lw[1], lw[2], lw[3]);
}

// ---------------- QKV GEMM via mma.sync bf16 (unchanged from R4) ----------------
#define SM_QKV 65536
__global__ void __launch_bounds__(256, 2)
qkv_mma_kern(int layer) {
    extern __shared__ char smem[];
    uint32_t sb = smem_u32(smem);
    int t = threadIdx.x, lane = t & 31, wid = t >> 5;
    int mt = blockIdx.x, ntile = blockIdx.y;
    int wm = wid & 1, wn = wid >> 1;

    float acc[4][4][4];
    #pragma unroll
    for (int a = 0; a < 4; a++)
        #pragma unroll
        for (int b = 0; b < 4; b++)
            #pragma unroll
            for (int c = 0; c < 4; c++) acc[a][b][c] = 0.f;

    auto issue_copy = [&](int c) {
        int s = c & 1;
        int akc = (c < 4) ? c : ((c < 8) ? c - 4 : c - 8);
        const uint4* Ap = ((c >= 4 && c < 8) ? g_xlo : g_xhi) + (size_t)(mt*4 + akc)*1024;
        int bkc = (c < 8) ? (c & 3) : (c - 8);
        const uint4* Bp = ((c < 8) ? g_whi : g_wlo) + (size_t)((layer*10 + ntile)*4 + bkc)*1024;
        uint32_t sa = sb + s*32768;
        #pragma unroll
        for (int i = 0; i < 4; i++)
            cp_async16(sa + (t + i*256)*16, Ap + t + i*256);
        uint32_t sbB = sa + 16384;
        #pragma unroll
        for (int i = 0; i < 4; i++)
            cp_async16(sbB + (t + i*256)*16, Bp + t + i*256);
        cp_commit();
    };

    issue_copy(0);
    #pragma unroll 1
    for (int c = 0; c < 12; c++) {
        int s = c & 1;
        if (c < 11) { issue_copy(c + 1); cp_wait<1>(); }
        else        { cp_wait<0>(); }
        __syncthreads();
        uint32_t Ab = sb + s*32768;
        uint32_t Bb = Ab + 16384;
        #pragma unroll
        for (int ks = 0; ks < 4; ks++) {
            uint32_t afr[4][4];
            #pragma unroll
            for (int mf = 0; mf < 4; mf++) {
                uint32_t off = (uint32_t)(wm*64 + mf*16 + (lane & 15))*128
                             + ks*32 + (lane >> 4)*16;
                ldsm_x4(afr[mf], Ab + sw128(off));
            }
            uint32_t bfr[4][2];
            #pragma unroll
            for (int nf = 0; nf < 4; nf++) {
                uint32_t off = (uint32_t)(wn*32 + nf*8 + (lane & 7))*128
                             + ks*32 + ((lane >> 3) & 1)*16;
                ldsm_x2(bfr[nf], Bb + sw128(off));
            }
            #pragma unroll
            for (int mf = 0; mf < 4; mf++)
                #pragma unroll
                for (int nf = 0; nf < 4; nf++)
                    mma16816(acc[mf][nf], afr[mf], bfr[nf]);
        }
        __syncthreads();
    }
    int rbase = mt*128 + wm*64 + (lane >> 2);
    int cbase = ntile*128 + wn*32 + (lane & 3)*2;
    #pragma unroll
    for (int mf = 0; mf < 4; mf++) {
        #pragma unroll
        for (int nf = 0; nf < 4; nf++) {
            size_t o0 = (size_t)(rbase + mf*16)*FIVEC + cbase + nf*8;
            *(float2*)&g_qkv[o0]           = make_float2(acc[mf][nf][0], acc[mf][nf][1]);
            *(float2*)&g_qkv[o0 + 8*FIVEC] = make_float2(acc[mf][nf][2], acc[mf][nf][3]);
        }
    }
}

// ================= tensor-core attention =================
// QK-type GEMM body: M=96, N=96, K=32, 3 hi/lo passes. Warp grid 2(m)x4(n).
// A rows [m][d] 128B rows; B rows [n][d] 128B rows. Buffers: A_hi, A_lo, B_hi, B_lo.
__device__ __forceinline__ void qk_gemm_3pass(uint32_t sb, uint32_t AHI, uint32_t ALO,
                                              uint32_t BHI, uint32_t BLO,
                                              int lane, int wm, int wn,
                                              float acc[3][3][4]) {
    uint32_t pa[3] = {AHI, ALO, AHI};
    uint32_t pb[3] = {BHI, BHI, BLO};
    #pragma unroll
    for (int ps = 0; ps < 3; ps++) {
        uint32_t Ab = sb + pa[ps], Bb = sb + pb[ps];
        #pragma unroll
        for (int ks = 0; ks < 2; ks++) {
            uint32_t afr[3][4];
            #pragma unroll
            for (int mf = 0; mf < 3; mf++) {
                uint32_t off = (uint32_t)(wm*48 + mf*16 + (lane & 15))*128
                             + ks*32 + (lane >> 4)*16;
                ldsm_x4(afr[mf], Ab + sw128(off));
            }
            uint32_t bfr[3][2];
            #pragma unroll
            for (int nf = 0; nf < 3; nf++) {
                uint32_t off = (uint32_t)(wn*24 + nf*8 + (lane & 7))*128
                             + ks*32 + ((lane >> 3) & 1)*16;
                ldsm_x2(bfr[nf], Bb + sw128(off));
            }
            #pragma unroll
            for (int mf = 0; mf < 3; mf++)
                #pragma unroll
                for (int nf = 0; nf < 3; nf++)
                    mma16816(acc[mf][nf], afr[mf], bfr[nf]);
        }
    }
}

// AV-type GEMM body: M=96 (rows), N=32 (d), K=96 (p in 2 chunks of 64/32), 3 passes.
// A chunks [m][p] 128B rows (c0: p<64, c1: p-64); V chunks [d][p] same.
__device__ __forceinline__ void av_gemm_3pass(uint32_t sb,
                                              uint32_t AHI0, uint32_t AHI1,
                                              uint32_t ALO0, uint32_t ALO1,
                                              uint32_t VHI0, uint32_t VHI1,
                                              uint32_t VLO0, uint32_t VLO1,
                                              int lane, int wm, int wn,
                                              float acc2[3][4]) {
    uint32_t pa0[3] = {AHI0, ALO0, AHI0}, pa1[3] = {AHI1, ALO1, AHI1};
    uint32_t pv0[3] = {VHI0, VHI0, VLO0}, pv1[3] = {VHI1, VHI1, VLO1};
    #pragma unroll
    for (int ps = 0; ps < 3; ps++) {
        #pragma unroll
        for (int ch = 0; ch < 2; ch++) {
            uint32_t Ab = sb + (ch ? pa1[ps] : pa0[ps]);
            uint32_t Vb = sb + (ch ? pv1[ps] : pv0[ps]);
            int nks = ch ? 2 : 4;
            #pragma unroll
            for (int ks = 0; ks < 4; ks++) {
                if (ks >= nks) break;
                uint32_t afr[3][4];
                #pragma unroll
                for (int mf = 0; mf < 3; mf++) {
                    uint32_t off = (uint32_t)(wm*48 + mf*16 + (lane & 15))*128
                                 + ks*32 + (lane >> 4)*16;
                    ldsm_x4(afr[mf], Ab + sw128(off));
                }
                uint32_t bfr[2];
                {
                    uint32_t off = (uint32_t)(wn*8 + (lane & 7))*128
                                 + ks*32 + ((lane >> 3) & 1)*16;
                    ldsm_x2(bfr, Vb + sw128(off));
                }
                #pragma unroll
                for (int mf = 0; mf < 3; mf++)
                    mma16816(acc2[mf], afr[mf], bfr);
            }
        }
    }
}

// ---------------- s1: per (b,h,i) — S1 = Q·K1^T on tensor cores ----------------
// smem: Qhi@0, Qlo@12288, Khi@24576, Klo@36864  (each 96x64 bf16 rows of 128B = 12KB)
#define SM_S1 49152
__global__ void __launch_bounds__(256)
s1_mma_kern() {
    extern __shared__ char smem[];
    uint32_t sb = smem_u32(smem);
    int t = threadIdx.x, lane = t & 31, wid = t >> 5;
    int wm = wid & 1, wn = wid >> 1;
    int bhi = blockIdx.x;
    int i = bhi % NT, bh = bhi / NT;
    int h = bh % HH, b = bh / HH;
    int baseQ = (b*NN + i*NT)*FIVEC + h*DD;
    int baseK = baseQ + CC;
    for (int idx = t; idx < 384; idx += 256) {
        int r = idx >> 2, g = idx & 3;
        uint32_t sw = sw128((uint32_t)(r*128 + g*16));
        cvt8(g_qkv + baseQ + r*FIVEC + g*8, sb + sw,        sb + 12288 + sw);
        cvt8(g_qkv + baseK + r*FIVEC + g*8, sb + 24576 + sw, sb + 36864 + sw);
    }
    __syncthreads();
    float acc[3][3][4];
    #pragma unroll
    for (int a = 0; a < 3; a++)
        #pragma unroll
        for (int bq = 0; bq < 3; bq++)
            #pragma unroll
            for (int c = 0; c < 4; c++) acc[a][bq][c] = 0.f;
    qk_gemm_3pass(sb, 0, 12288, 24576, 36864, lane, wm, wn, acc);
    size_t base = (size_t)(bh*NT + i) * NN;
    int rbase = wm*48 + (lane >> 2);
    int cbase = wn*24 + (lane & 3)*2;
    #pragma unroll
    for (int mf = 0; mf < 3; mf++) {
        #pragma unroll
        for (int nf = 0; nf < 3; nf++) {
            int row = rbase + mf*16, col = cbase + nf*8;
            *(float2*)&g_S[base + (size_t)row*NT + col]     = make_float2(acc[mf][nf][0], acc[mf][nf][1]);
            *(float2*)&g_S[base + (size_t)(row+8)*NT + col] = make_float2(acc[mf][nf][2], acc[mf][nf][3]);
        }
    }
}

// ---------------- s2: per (b,h,j) — S2 GEMM + S1 add + softmax + A·V2 GEMM ----------------
// smem layout (bytes):
//   0      : Qhi (12KB) / reused Ahi_c0
//   12288  : Qlo        / reused Ahi_c1
//   24576  : K2hi       / reused Alo_c0
//   36864  : K2lo       / reused Alo_c1
//   49152  : Ss 96x100 fp32 (38400)
//   87552  : Vhi_c0 (4KB), 91648 Vhi_c1, 95744 Vlo_c0, 99840 Vlo_c1
#define SM_S2M (87552 + 16384)
__global__ void __launch_bounds__(256)
s2_mma_kern(float* __restrict__ Xout) {
    extern __shared__ char smem[];
    uint32_t sb = smem_u32(smem);
    float* Ss = (float*)(smem + 49152);
    int t = threadIdx.x, lane = t & 31, wid = t >> 5;
    int wm = wid & 1, wn = wid >> 1;
    int bhj = blockIdx.x;
    int j = bhj % NT, bh = bhj / NT;
    int h = bh % HH, b = bh / HH;
    int baseQ = (b*NN + j)*FIVEC + h*DD;        // + i*NT*FIVEC
    int baseK2 = baseQ + 2*CC;                   // K2[p,j,d]
    int baseV2 = baseQ + 4*CC;                   // V2[p,j,d]

    for (int idx = t; idx < 384; idx += 256) {
        int r = idx >> 2, g = idx & 3;
        uint32_t sw = sw128((uint32_t)(r*128 + g*16));
        cvt8(g_qkv + baseQ  + r*NT*FIVEC + g*8, sb + sw,         sb + 12288 + sw);
        cvt8(g_qkv + baseK2 + r*NT*FIVEC + g*8, sb + 24576 + sw, sb + 36864 + sw);
    }
    __syncthreads();
    float acc[3][3][4];
    #pragma unroll
    for (int a = 0; a < 3; a++)
        #pragma unroll
        for (int bq = 0; bq < 3; bq++)
            #pragma unroll
            for (int c = 0; c < 4; c++) acc[a][bq][c] = 0.f;
    qk_gemm_3pass(sb, 0, 12288, 24576, 36864, lane, wm, wn, acc);

    // epilogue into Ss with S1 add + scale (rows = i, cols = p)
    size_t sBase = (size_t)bh * NT * NN + (size_t)j * NT;
    {
        int rbase = wm*48 + (lane >> 2);
        int cbase = wn*24 + (lane & 3)*2;
        #pragma unroll
        for (int mf = 0; mf < 3; mf++) {
            #pragma unroll
            for (int nf = 0; nf < 3; nf++) {
                int row = rbase + mf*16, col = cbase + nf*8;
                float2 s1a = *(const float2*)&g_S[sBase + (size_t)row*NN + col];
                float2 s1b = *(const float2*)&g_S[sBase + (size_t)(row+8)*NN + col];
                Ss[row*100 + col]       = (acc[mf][nf][0] + s1a.x) * SCALE_L2E;
                Ss[row*100 + col + 1]   = (acc[mf][nf][1] + s1a.y) * SCALE_L2E;
                Ss[(row+8)*100 + col]   = (acc[mf][nf][2] + s1b.x) * SCALE_L2E;
                Ss[(row+8)*100 + col+1] = (acc[mf][nf][3] + s1b.y) * SCALE_L2E;
            }
        }
    }
    __syncthreads();
    // softmax per row (base-2), write A to g_S for o1
    for (int i = wid; i < 96; i += 8) {
        float v0 = Ss[i*100 + lane];
        float v1 = Ss[i*100 + 32 + lane];
        float v2 = Ss[i*100 + 64 + lane];
        float mx = fmaxf(v0, fmaxf(v1, v2));
        #pragma unroll
        for (int o = 16; o; o >>= 1) mx = fmaxf(mx, __shfl_xor_sync(0xffffffffu, mx, o));
        v0 = ex2f(v0 - mx); v1 = ex2f(v1 - mx); v2 = ex2f(v2 - mx);
        float s = v0 + v1 + v2;
        #pragma unroll
        for (int o = 16; o; o >>= 1) s += __shfl_xor_sync(0xffffffffu, s, o);
        float inv = 1.f / s;
        v0 *= inv; v1 *= inv; v2 *= inv;
        Ss[i*100 + lane] = v0;
        Ss[i*100 + 32 + lane] = v1;
        Ss[i*100 + 64 + lane] = v2;
        g_S[sBase + (size_t)i*NN + lane]      = v0;
        g_S[sBase + (size_t)i*NN + 32 + lane] = v1;
        g_S[sBase + (size_t)i*NN + 64 + lane] = v2;
    }
    __syncthreads();
    // convert A (from Ss) into hi/lo chunk tiles (reusing QK buffers)
    for (int idx = t; idx < 96*12; idx += 256) {
        int r = idx / 12, g = idx % 12;
        const float* arow = &Ss[r*100 + g*8];
        float v[8] = {arow[0],arow[1],arow[2],arow[3],arow[4],arow[5],arow[6],arow[7]};
        uint32_t hw[4], lw[4];
        #pragma unroll
        for (int jj = 0; jj < 4; jj++) split2(v[2*jj], v[2*jj+1], hw[jj], lw[jj]);
        uint32_t hbase = (g < 8) ? 0u : 12288u;
        uint32_t lbase = (g < 8) ? 24576u : 36864u;
        uint32_t off = (uint32_t)r*128 + (uint32_t)((g < 8) ? g : g - 8)*16;
        uint32_t sw = sw128(off);
        sts128(sb + hbase + sw, hw[0], hw[1], hw[2], hw[3]);
        sts128(sb + lbase + sw, lw[0], lw[1], lw[2], lw[3]);
    }
    // convert V2 transposed to Vt[d][p] chunks
    for (int idx = t; idx < 32*48; idx += 256) {
        int d = idx / 48, p2 = idx % 48, p = p2*2;
        float v0 = g_qkv[baseV2 + (size_t)p*NT*FIVEC + d];
        float v1 = g_qkv[baseV2 + (size_t)(p+1)*NT*FIVEC + d];
        uint32_t hw, lw;
        split2(v0, v1, hw, lw);
        uint32_t hbase = (p < 64) ? 87552u : 91648u;
        uint32_t lbase = (p < 64) ? 95744u : 99840u;
        uint32_t off = (uint32_t)d*128 + (uint32_t)((p < 64) ? p : p - 64)*2;
        uint32_t sw = sw128(off);
        sts32(sb + hbase + sw, hw);
        sts32(sb + lbase + sw, lw);
    }
    __syncthreads();
    // AV GEMM: O2[i,d]
    float acc2[3][4];
    #pragma unroll
    for (int a = 0; a < 3; a++)
        #pragma unroll
        for (int c = 0; c < 4; c++) acc2[a][c] = 0.f;
    av_gemm_3pass(sb, 0, 12288, 24576, 36864, 87552, 91648, 95744, 99840,
                  lane, wm, wn, acc2);
    {
        int rbase = wm*48 + (lane >> 2);
        int col = wn*8 + (lane & 3)*2;
        #pragma unroll
        for (int mf = 0; mf < 3; mf++) {
            int row = rbase + mf*16;
            size_t o0 = (size_t)(b*NN + row*NT + j)*CC + h*DD + col;
            size_t o1 = (size_t)(b*NN + (row+8)*NT + j)*CC + h*DD + col;
            *(float2*)&Xout[o0] = make_float2(acc2[mf][0], acc2[mf][1]);
            *(float2*)&Xout[o1] = make_float2(acc2[mf][2], acc2[mf][3]);
        }
    }
}

// ---------------- o1: per (b,h,i) — O1 = A·V1 on tensor, accumulate into Xout ----------------
// smem: Ahi_c0@0, Ahi_c1@12288, Alo_c0@24576, Alo_c1@36864,
//       Vhi_c0@49152, Vhi_c1@53248, Vlo_c0@57344, Vlo_c1@61440
#define SM_O1M 65536
__global__ void __launch_bounds__(256)
o1_mma_kern(float* __restrict__ Xout) {
    extern __shared__ char smem[];
    uint32_t sb = smem_u32(smem);
    int t = threadIdx.x, lane = t & 31, wid = t >> 5;
    int wm = wid & 1, wn = wid >> 1;
    int bhi = blockIdx.x;
    int i = bhi % NT, bh = bhi / NT;
    int h = bh % HH, b = bh / HH;
    size_t aBase = (size_t)(bh*NT + i) * NN;     // A[j][p] rows contiguous
    int baseV = (b*NN + i*NT)*FIVEC + 3*CC + h*DD;  // V1[p,d]: + p*FIVEC + d

    for (int idx = t; idx < 96*12; idx += 256) {
        int r = idx / 12, g = idx % 12;
        const float* arow = &g_S[aBase + (size_t)r*NT + g*8];
        float4 f0 = *(const float4*)arow;
        float4 f1 = *(const float4*)(arow + 4);
        float v[8] = {f0.x,f0.y,f0.z,f0.w,f1.x,f1.y,f1.z,f1.w};
        uint32_t hw[4], lw[4];
        #pragma unroll
        for (int jj = 0; jj < 4; jj++) split2(v[2*jj], v[2*jj+1], hw[jj], lw[jj]);
        uint32_t hbase = (g < 8) ? 0u : 12288u;
        uint32_t lbase = (g < 8) ? 24576u : 36864u;
        uint32_t off = (uint32_t)r*128 + (uint32_t)((g < 8) ? g : g - 8)*16;
        uint32_t sw = sw128(off);
        sts128(sb + hbase + sw, hw[0], hw[1], hw[2], hw[3]);
        sts128(sb + lbase + sw, lw[0], lw[1], lw[2], lw[3]);
    }
    for (int idx = t; idx < 32*48; idx += 256) {
        int d = idx / 48, p2 = idx % 48, p = p2*2;
        float v0 = g_qkv[baseV + (size_t)p*FIVEC + d];
        float v1 = g_qkv[baseV + (size_t)(p+1)*FIVEC + d];
        uint32_t hw, lw;
        split2(v0, v1, hw, lw);
        uint32_t hbase = (p < 64) ? 49152u : 53248u;
        uint32_t lbase = (p < 64) ? 57344u : 61440u;
        uint32_t off = (uint32_t)d*128 + (uint32_t)((p < 64) ? p : p - 64)*2;
        uint32_t sw = sw128(off);
        sts32(sb + hbase + sw, hw);
        sts32(sb + lbase + sw, lw);
    }
    __syncthreads();
    float acc2[3][4];
    #pragma unroll
    for (int a = 0; a < 3; a++)
        #pragma unroll
        for (int c = 0; c < 4; c++) acc2[a][c] = 0.f;
    av_gemm_3pass(sb, 0, 12288, 24576, 36864, 49152, 53248, 57344, 61440,
                  lane, wm, wn, acc2);
    {
        int rbase = wm*48 + (lane >> 2);
        int col = wn*8 + (lane & 3)*2;
        #pragma unroll
        for (int mf = 0; mf < 3; mf++) {
            int row = rbase + mf*16;   // j
            size_t o0 = (size_t)(b*NN + i*NT + row)*CC + h*DD + col;
            size_t o1 = (size_t)(b*NN + i*NT + row + 8)*CC + h*DD + col;
            float2 a0 = *(const float2*)&Xout[o0];
            float2 a1 = *(const float2*)&Xout[o1];
            *(float2*)&Xout[o0] = make_float2(a0.x + acc2[mf][0], a0.y + acc2[mf][1]);
            *(float2*)&Xout[o1] = make_float2(a1.x + acc2[mf][2], a1.y + acc2[mf][3]);
        }
    }
}

// ---------------- pooling + head ----------------
__global__ void pool1_kern(const float* __restrict__ X) {
    int bi = blockIdx.x;
    int b = bi / NT, i = bi % NT;
    int c = threadIdx.x;
    float s = 0.f;
    for (int j = 0; j < NT; j++)
        s += X[(size_t)(b*NN + i*NT + j)*CC + c];
    g_pool[bi*CC + c] = s;
}

__global__ void pool2_head_kern(const float* __restrict__ W,
                                const float* __restrict__ bias,
                                float* __restrict__ out) {
    int b = blockIdx.x;
    __shared__ float xb[CC];
    int c = threadIdx.x;
    float s = 0.f;
    for (int i = 0; i < NT; i++)
        s += g_pool[(b*NT + i)*CC + c];
    xb[c] = s * (1.f / (float)NN);
    __syncthreads();
    float acc = bias[c];
    #pragma unroll 8
    for (int ci = 0; ci < CC; ci++)
        acc += xb[ci] * W[c*CC + ci];
    out[b*CC + c] = acc;
}

// ---------------- launch ----------------
extern "C" void kernel_launch(void* const* d_in, const int* in_sizes, int n_in,
                              void* d_out, int out_size) {
    const int*   adj   = (const int*)d_in[0];
    const float* emb   = (const float*)d_in[1];
    const float* qkvw  = (const float*)d_in[2];
    const float* headw = (const float*)d_in[3];
    const float* headb = (const float*)d_in[4];
    float* out = (float*)d_out;

    float *bufA, *bufB;
    cudaGetSymbolAddress((void**)&bufA, g_bufA);
    cudaGetSymbolAddress((void**)&bufB, g_bufB);

    cudaFuncSetAttribute(qkv_mma_kern, cudaFuncAttributeMaxDynamicSharedMemorySize, SM_QKV);
    cudaFuncSetAttribute(s1_mma_kern,  cudaFuncAttributeMaxDynamicSharedMemorySize, SM_S1);
    cudaFuncSetAttribute(s2_mma_kern,  cudaFuncAttributeMaxDynamicSharedMemorySize, SM_S2M);
    cudaFuncSetAttribute(o1_mma_kern,  cudaFuncAttributeMaxDynamicSharedMemorySize, SM_O1M);

    detect_adj_kern<<<1, 256>>>((const unsigned int*)adj, BB*NN);
    embed_kern<<<1024, 256>>>(adj, emb, bufA);
    convert_w_kern<<<(DEPTH*FIVEC*32 + 255)/256, 256>>>(qkvw);

    for (int l = 0; l < DEPTH; l++) {
        float* cur = (l & 1) ? bufB : bufA;
        float* nxt = (l & 1) ? bufA : bufB;
        red1_kern<<<1024, 256>>>(cur);
        red2_kern<<<1, 256>>>();
        convert_x_kern<<<(MM*32 + 255)/256, 256>>>(cur);
        qkv_mma_kern<<<dim3(MM/128, FIVEC/128), 256, SM_QKV>>>(l);
        s1_mma_kern<<<BB*HH*NT, 256, SM_S1>>>();
        s2_mma_kern<<<BB*HH*NT, 256, SM_S2M>>>(nxt);
        o1_mma_kern<<<BB*HH*NT, 256, SM_O1M>>>(nxt);
    }
    pool1_kern<<<BB*NT, 256>>>(bufA);
    pool2_head_kern<<<BB, 256>>>(headw, headb, out);
}